// round 7
// baseline (speedup 1.0000x reference)
#include <cuda_runtime.h>
#include <cuda_bf16.h>
#include <cstdint>
#include <cstddef>

// ============================================================================
// helpers (base sm_103 ISA only: ldmatrix + mma.sync + cp.async)
// ============================================================================
__device__ __forceinline__ uint32_t smem_u32(const void* p) {
    uint32_t a;
    asm("{ .reg .u64 t; cvta.to.shared.u64 t, %1; cvt.u32.u64 %0, t; }"
        : "=r"(a) : "l"(p));
    return a;
}

#define CP16(dst, src) \
    asm volatile("cp.async.cg.shared.global [%0], [%1], 16;" \
                 :: "r"(dst), "l"(src) : "memory")
#define CP_COMMIT() asm volatile("cp.async.commit_group;" ::: "memory")
#define CP_WAIT1()  asm volatile("cp.async.wait_group 1;" ::: "memory")
#define CP_WAIT0()  asm volatile("cp.async.wait_group 0;" ::: "memory")

#define LDSM4(r, addr) \
    asm volatile("ldmatrix.sync.aligned.m8n8.x4.shared.b16 {%0,%1,%2,%3}, [%4];" \
                 : "=r"((r)[0]), "=r"((r)[1]), "=r"((r)[2]), "=r"((r)[3]) : "r"(addr))

#define MMA16816(d, a, b0, b1) \
    asm volatile("mma.sync.aligned.m16n8k16.row.col.f32.bf16.bf16.f32 " \
                 "{%0,%1,%2,%3},{%4,%5,%6,%7},{%8,%9},{%0,%1,%2,%3};" \
                 : "+f"((d)[0]), "+f"((d)[1]), "+f"((d)[2]), "+f"((d)[3]) \
                 : "r"((a)[0]), "r"((a)[1]), "r"((a)[2]), "r"((a)[3]), \
                   "r"(b0), "r"(b1))

#define STS128U(addr, r) \
    asm volatile("st.shared.v4.b32 [%0], {%1, %2, %3, %4};" \
                 :: "r"(addr), "r"((r)[0]), "r"((r)[1]), "r"((r)[2]), "r"((r)[3]) : "memory")

__device__ __forceinline__ uint32_t packbf2(float f0, float f1) {
    __nv_bfloat162 t(__float2bfloat16(f0), __float2bfloat16(f1));
    return *reinterpret_cast<uint32_t*>(&t);
}

// ============================================================================
// Scratch (device globals; no allocations allowed)
// ============================================================================
__device__ __align__(16) __nv_bfloat16 g_w_hi[6 * 1048576];   // [M1,M2,Wq,Wk,Wv,Wo]
__device__ __align__(16) __nv_bfloat16 g_w_lo[6 * 1048576];
__device__ __align__(16) __nv_bfloat16 g_enh_hi[4194304], g_enh_lo[4194304]; // [mem;x]
__device__ __align__(16) __nv_bfloat16 g_h_hi[2097152],  g_h_lo[2097152];
__device__ __align__(16) __nv_bfloat16 g_q_hi[4194304],  g_q_lo[4194304];
__device__ __align__(16) __nv_bfloat16 g_k_hi[4194304],  g_k_lo[4194304];
__device__ __align__(16) __nv_bfloat16 g_vt_hi[4194304], g_vt_lo[4194304];   // [32][64][2048]
__device__ __align__(16) __nv_bfloat16 g_ctx_hi[2097152], g_ctx_lo[2097152];
__device__ __align__(16) float g_sc[16777216];   // 67 MB: raw scores for 4 heads (L2-hot)

// ============================================================================
// fp32 -> (bf16 hi, bf16 lo) conversions
// ============================================================================
__global__ void __launch_bounds__(256) conv_w_kernel(
    const float* __restrict__ s0, const float* __restrict__ s1,
    const float* __restrict__ s2, const float* __restrict__ s3,
    const float* __restrict__ s4, const float* __restrict__ s5,
    __nv_bfloat16* __restrict__ hi, __nv_bfloat16* __restrict__ lo)
{
    const int w = blockIdx.y;
    const float* src = (w == 0) ? s0 : (w == 1) ? s1 : (w == 2) ? s2
                    : (w == 3) ? s3 : (w == 4) ? s4 : s5;
    hi += (size_t)w * 1048576;
    lo += (size_t)w * 1048576;
    int i = blockIdx.x * 256 + threadIdx.x;           // n4 = 262144
    float4 v = reinterpret_cast<const float4*>(src)[i];
    float vals[4] = {v.x, v.y, v.z, v.w};
    __nv_bfloat16 h[4], l[4];
#pragma unroll
    for (int j = 0; j < 4; ++j) {
        h[j] = __float2bfloat16(vals[j]);
        l[j] = __float2bfloat16(vals[j] - __bfloat162float(h[j]));
    }
    reinterpret_cast<__nv_bfloat162*>(hi)[2 * i]     = {h[0], h[1]};
    reinterpret_cast<__nv_bfloat162*>(hi)[2 * i + 1] = {h[2], h[3]};
    reinterpret_cast<__nv_bfloat162*>(lo)[2 * i]     = {l[0], l[1]};
    reinterpret_cast<__nv_bfloat162*>(lo)[2 * i + 1] = {l[2], l[3]};
}

__global__ void __launch_bounds__(256) conv_kernel(
    const float* __restrict__ src, __nv_bfloat16* __restrict__ hi,
    __nv_bfloat16* __restrict__ lo, int n4)
{
    int i = blockIdx.x * 256 + threadIdx.x;
    if (i >= n4) return;
    float4 v = reinterpret_cast<const float4*>(src)[i];
    float vals[4] = {v.x, v.y, v.z, v.w};
    __nv_bfloat16 h[4], l[4];
#pragma unroll
    for (int j = 0; j < 4; ++j) {
        h[j] = __float2bfloat16(vals[j]);
        l[j] = __float2bfloat16(vals[j] - __bfloat162float(h[j]));
    }
    reinterpret_cast<__nv_bfloat162*>(hi)[2 * i]     = {h[0], h[1]};
    reinterpret_cast<__nv_bfloat162*>(hi)[2 * i + 1] = {h[2], h[3]};
    reinterpret_cast<__nv_bfloat162*>(lo)[2 * i]     = {l[0], l[1]};
    reinterpret_cast<__nv_bfloat162*>(lo)[2 * i + 1] = {l[2], l[3]};
}

// ============================================================================
// bf16x3 NT GEMM via mma.sync: C = act(scale*(A@B^T) + bias)
// CTA tile 128 x 64, BK=32, 3-stage cp.async pipeline, 1 barrier per chunk.
// 3 fused passes per K-chunk: Ahi*Bhi + Alo*Bhi + Ahi*Blo, fp32 reg accum.
// MODE 0: plain    MODE 1: QK (z=zbase+bz; C=scratch local z)
// MODE 2: AV       A from fp32 attn lower half (__ldcs) + in-kernel hi/lo split
// transV: scatter C into Vt[32][64][2048]
// ============================================================================
template <int MODE>
__global__ void __launch_bounds__(256, 2) gemm3_mma(
    const __nv_bfloat16* __restrict__ Ahi, const __nv_bfloat16* __restrict__ Alo,
    const float* __restrict__ Af,
    const __nv_bfloat16* __restrict__ Bhi, const __nv_bfloat16* __restrict__ Blo,
    const float* __restrict__ bias,
    float* __restrict__ Cf, __nv_bfloat16* __restrict__ Chi, __nv_bfloat16* __restrict__ Clo,
    int K, int lda, int ldb, int ldc,
    float scale, int relu, int zbase, int transV)
{
    extern __shared__ __align__(128) char smem[];
    constexpr int STRIDE = 80;                  // 64B row + 16B pad
    constexpr int A_BYTES = 128 * STRIDE;       // 10240
    constexpr int B_BYTES = 64 * STRIDE;        // 5120
    constexpr int STAGE = 2 * A_BYTES + 2 * B_BYTES;   // 30720

    const int tid = threadIdx.x;
    const int wid = tid >> 5, lid = tid & 31;
    const int m0 = blockIdx.y * 128;
    const int n0 = blockIdx.x * 64;
    const int z  = (MODE == 1) ? (zbase + blockIdx.z) : blockIdx.z;

    const int r0 = wid * 16;                    // 8 warps x 16 rows = 128

    size_t aOff = 0, bOff = 0;
    if (MODE == 1) {
        aOff = bOff = (size_t)(z >> 4) * 2097152 + (size_t)(z & 15) * 64;
    } else if (MODE == 2) {
        bOff = (size_t)z * 131072;
    }
    if (MODE != 2) { Ahi += aOff; Alo += aOff; }
    Bhi += bOff; Blo += bOff;

    const uint32_t sbase = smem_u32(smem);

    auto issueA = [&](int c) {
        const int kt = c << 5;
        const uint32_t sb = sbase + (c % 3) * STAGE;
#pragma unroll
        for (int u = 0; u < 2; ++u) {
            int id = tid + u * 256;
            int row = id >> 2, seg = id & 3;
            const char* sH = (const char*)(Ahi + (size_t)(m0 + row) * lda + kt) + seg * 16;
            const char* sL = (const char*)(Alo + (size_t)(m0 + row) * lda + kt) + seg * 16;
            uint32_t d = sb + row * STRIDE + seg * 16;
            CP16(d, sH);
            CP16(d + A_BYTES, sL);
        }
    };
    auto issueB = [&](int c) {
        const int kt = c << 5;
        const uint32_t sb = sbase + (c % 3) * STAGE;
        int row = tid >> 2, seg = tid & 3;       // 64 rows x 4 segs = 256
        const char* sH = (const char*)(Bhi + (size_t)(n0 + row) * ldb + kt) + seg * 16;
        const char* sL = (const char*)(Blo + (size_t)(n0 + row) * ldb + kt) + seg * 16;
        uint32_t d = sb + 2 * A_BYTES + row * STRIDE + seg * 16;
        CP16(d, sH);
        CP16(d + B_BYTES, sL);
    };

    float acc[8][4];
#pragma unroll
    for (int j = 0; j < 8; ++j)
#pragma unroll
        for (int q = 0; q < 4; ++q) acc[j][q] = 0.0f;

    const uint32_t aRow = (uint32_t)(r0 + (lid & 15)) * STRIDE + ((lid >> 4) & 1) * 16;
    const uint32_t bRow = (uint32_t)((lid & 7) + ((lid >> 4) & 1) * 8) * STRIDE
                        + ((lid >> 3) & 1) * 16;

    auto mma_chunk = [&](int c) {
        const uint32_t sb = sbase + (c % 3) * STAGE;
        const uint32_t aH = sb, aL = sb + A_BYTES;
        const uint32_t bH = sb + 2 * A_BYTES, bL = bH + B_BYTES;
#pragma unroll
        for (int s = 0; s < 2; ++s) {
            uint32_t ah[4], al[4], bb[4][4];
            LDSM4(ah, aH + aRow + s * 32);
            LDSM4(al, aL + aRow + s * 32);
#pragma unroll
            for (int j = 0; j < 4; ++j)
                LDSM4(bb[j], bH + bRow + j * 16 * STRIDE + s * 32);
#pragma unroll
            for (int jt = 0; jt < 8; ++jt) {
                MMA16816(acc[jt], ah, bb[jt >> 1][(jt & 1) * 2], bb[jt >> 1][(jt & 1) * 2 + 1]);
                MMA16816(acc[jt], al, bb[jt >> 1][(jt & 1) * 2], bb[jt >> 1][(jt & 1) * 2 + 1]);
            }
#pragma unroll
            for (int j = 0; j < 4; ++j)
                LDSM4(bb[j], bL + bRow + j * 16 * STRIDE + s * 32);
#pragma unroll
            for (int jt = 0; jt < 8; ++jt)
                MMA16816(acc[jt], ah, bb[jt >> 1][(jt & 1) * 2], bb[jt >> 1][(jt & 1) * 2 + 1]);
        }
    };

    const int nC = K >> 5;

    if constexpr (MODE != 2) {
        issueA(0); issueB(0); CP_COMMIT();
        if (nC > 1) { issueA(1); issueB(1); }
        CP_COMMIT();
        for (int c = 0; c < nC; ++c) {
            if (c == nC - 1) { CP_WAIT0(); } else { CP_WAIT1(); }
            __syncthreads();
            if (c + 2 < nC) { issueA(c + 2); issueB(c + 2); CP_COMMIT(); }
            mma_chunk(c);
        }
    } else {
        // A from fp32 attn (lower half): reg-staged __ldcs + convert + STS
        const float* Abase = Af + (size_t)z * 4194304 + (size_t)1024 * 2048;
        const int arow = tid >> 1, acol = (tid & 1) * 16;
        const float* Aptr = Abase + (size_t)(m0 + arow) * 2048 + acol;

        auto ldA = [&](int c, float4* r) {
            const float4* p = reinterpret_cast<const float4*>(Aptr + (c << 5));
#pragma unroll
            for (int j = 0; j < 4; ++j) r[j] = __ldcs(p + j);
        };
        auto stsA = [&](int c, const float4* r) {
            const uint32_t sb = sbase + (c % 3) * STAGE;
            const uint32_t d = sb + arow * STRIDE + acol * 2;
#pragma unroll
            for (int half = 0; half < 2; ++half) {
                float f[4] = {r[2 * half].x, r[2 * half].y, r[2 * half].z, r[2 * half].w};
                float g4[4] = {r[2 * half + 1].x, r[2 * half + 1].y,
                               r[2 * half + 1].z, r[2 * half + 1].w};
                uint32_t hp[4], lp[4];
#pragma unroll
                for (int q = 0; q < 2; ++q) {
                    float f0 = f[2 * q], f1 = f[2 * q + 1];
                    __nv_bfloat16 h0 = __float2bfloat16(f0), h1 = __float2bfloat16(f1);
                    hp[q] = packbf2(f0, f1);
                    lp[q] = packbf2(f0 - __bfloat162float(h0), f1 - __bfloat162float(h1));
                }
#pragma unroll
                for (int q = 0; q < 2; ++q) {
                    float f0 = g4[2 * q], f1 = g4[2 * q + 1];
                    __nv_bfloat16 h0 = __float2bfloat16(f0), h1 = __float2bfloat16(f1);
                    hp[2 + q] = packbf2(f0, f1);
                    lp[2 + q] = packbf2(f0 - __bfloat162float(h0), f1 - __bfloat162float(h1));
                }
                STS128U(d + half * 16, hp);
                STS128U(d + half * 16 + A_BYTES, lp);
            }
        };

        float4 R0[4], R1[4], Rn[4];
        ldA(0, R0); ldA(1, R1);
        stsA(0, R0); stsA(1, R1);
        issueB(0); CP_COMMIT();
        issueB(1); CP_COMMIT();
        if (nC > 2) ldA(2, Rn);
        for (int c = 0; c < nC; ++c) {
            if (c == nC - 1) { CP_WAIT0(); } else { CP_WAIT1(); }
            __syncthreads();
            if (c + 2 < nC) {
                stsA(c + 2, Rn);
                issueB(c + 2); CP_COMMIT();
                if (c + 3 < nC) ldA(c + 3, Rn);
            }
            mma_chunk(c);
        }
    }

    // ---------------- epilogue ----------------
    size_t cOffZ = 0;
    if constexpr (MODE == 1)      cOffZ = (size_t)blockIdx.z * 4194304;     // local z in scratch
    else if constexpr (MODE == 2) cOffZ = (size_t)(z >> 4) * 1048576 + (size_t)(z & 15) * 64;

    const int grp = lid >> 2, tig = lid & 3;

#pragma unroll
    for (int jt = 0; jt < 8; ++jt) {
        const int mr = m0 + r0 + grp;
        const int nc = n0 + jt * 8 + tig * 2;
        float v0 = acc[jt][0] * scale, v1 = acc[jt][1] * scale;
        float v2 = acc[jt][2] * scale, v3 = acc[jt][3] * scale;
        if (bias) {
            float b0 = __ldg(bias + nc), b1 = __ldg(bias + nc + 1);
            v0 += b0; v1 += b1; v2 += b0; v3 += b1;
        }
        if (relu) {
            v0 = fmaxf(v0, 0.0f); v1 = fmaxf(v1, 0.0f);
            v2 = fmaxf(v2, 0.0f); v3 = fmaxf(v3, 0.0f);
        }
        if (Cf) {
            *reinterpret_cast<float2*>(&Cf[cOffZ + (size_t)mr * ldc + nc]) =
                make_float2(v0, v1);
            *reinterpret_cast<float2*>(&Cf[cOffZ + (size_t)(mr + 8) * ldc + nc]) =
                make_float2(v2, v3);
        }
        if (Chi) {
            __nv_bfloat16 h0 = __float2bfloat16(v0), h1 = __float2bfloat16(v1);
            __nv_bfloat16 h2 = __float2bfloat16(v2), h3 = __float2bfloat16(v3);
            __nv_bfloat16 l0 = __float2bfloat16(v0 - __bfloat162float(h0));
            __nv_bfloat16 l1 = __float2bfloat16(v1 - __bfloat162float(h1));
            __nv_bfloat16 l2 = __float2bfloat16(v2 - __bfloat162float(h2));
            __nv_bfloat16 l3 = __float2bfloat16(v3 - __bfloat162float(h3));
            if (!transV) {
                size_t i0 = cOffZ + (size_t)mr * ldc + nc;
                size_t i1 = cOffZ + (size_t)(mr + 8) * ldc + nc;
                *reinterpret_cast<__nv_bfloat162*>(&Chi[i0]) = {h0, h1};
                *reinterpret_cast<__nv_bfloat162*>(&Chi[i1]) = {h2, h3};
                *reinterpret_cast<__nv_bfloat162*>(&Clo[i0]) = {l0, l1};
                *reinterpret_cast<__nv_bfloat162*>(&Clo[i1]) = {l2, l3};
            } else {
#pragma unroll
                for (int e = 0; e < 4; ++e) {
                    int rr = mr + (e >> 1) * 8;
                    int nn = nc + (e & 1);
                    size_t idx = ((size_t)(rr >> 11) * 16 + (size_t)(nn >> 6)) * 131072
                               + (size_t)(nn & 63) * 2048 + (size_t)(rr & 2047);
                    __nv_bfloat16 hv = (e == 0) ? h0 : (e == 1) ? h1 : (e == 2) ? h2 : h3;
                    __nv_bfloat16 lv = (e == 0) ? l0 : (e == 1) ? l1 : (e == 2) ? l2 : l3;
                    Chi[idx] = hv;
                    Clo[idx] = lv;
                }
            }
        }
    }
}

// ============================================================================
// Row softmax: scratch (L2-hot, 4 heads) -> attn output (streaming .cs)
// ============================================================================
__global__ void __launch_bounds__(256) softmax_kernel(
    const float* __restrict__ scratch, float* __restrict__ attn, int zbase)
{
    const int zloc = blockIdx.x >> 11;
    const int rr = blockIdx.x & 2047;
    const float4* p = reinterpret_cast<const float4*>(
        scratch + (size_t)zloc * 4194304 + (size_t)rr * 2048);
    float4* q = reinterpret_cast<float4*>(
        attn + (size_t)(zbase + zloc) * 4194304 + (size_t)rr * 2048);
    const int tid = threadIdx.x;
    float4 v0 = p[tid];
    float4 v1 = p[tid + 256];

    float mx = fmaxf(fmaxf(fmaxf(v0.x, v0.y), fmaxf(v0.z, v0.w)),
                     fmaxf(fmaxf(v1.x, v1.y), fmaxf(v1.z, v1.w)));
#pragma unroll
    for (int o = 16; o; o >>= 1) mx = fmaxf(mx, __shfl_xor_sync(0xffffffffu, mx, o));

    __shared__ float smax[8], ssum[8];
    if ((tid & 31) == 0) smax[tid >> 5] = mx;
    __syncthreads();
    float m = smax[0];
#pragma unroll
    for (int i = 1; i < 8; i++) m = fmaxf(m, smax[i]);

    v0.x = __expf(v0.x - m); v0.y = __expf(v0.y - m);
    v0.z = __expf(v0.z - m); v0.w = __expf(v0.w - m);
    v1.x = __expf(v1.x - m); v1.y = __expf(v1.y - m);
    v1.z = __expf(v1.z - m); v1.w = __expf(v1.w - m);

    float s = v0.x + v0.y + v0.z + v0.w + v1.x + v1.y + v1.z + v1.w;
#pragma unroll
    for (int o = 16; o; o >>= 1) s += __shfl_xor_sync(0xffffffffu, s, o);
    if ((tid & 31) == 0) ssum[tid >> 5] = s;
    __syncthreads();
    float tot = 0.0f;
#pragma unroll
    for (int i = 0; i < 8; i++) tot += ssum[i];
    const float inv = 1.0f / tot;

    v0.x *= inv; v0.y *= inv; v0.z *= inv; v0.w *= inv;
    v1.x *= inv; v1.y *= inv; v1.z *= inv; v1.w *= inv;
    __stcs(q + tid, v0);
    __stcs(q + tid + 256, v1);
}

// ============================================================================
// Launch
// ============================================================================
extern "C" void kernel_launch(void* const* d_in, const int* in_sizes, int n_in,
                              void* d_out, int out_size)
{
    const float* x   = (const float*)d_in[0];
    const float* Wq  = (const float*)d_in[1];
    const float* bq  = (const float*)d_in[2];
    const float* Wk  = (const float*)d_in[3];
    const float* bk  = (const float*)d_in[4];
    const float* Wv  = (const float*)d_in[5];
    const float* bv  = (const float*)d_in[6];
    const float* Wo  = (const float*)d_in[7];
    const float* bo  = (const float*)d_in[8];
    const float* M1  = (const float*)d_in[9];
    const float* bm1 = (const float*)d_in[10];
    const float* M2  = (const float*)d_in[11];
    const float* bm2 = (const float*)d_in[12];

    float* out  = (float*)d_out;                      // (2,1024,1024)
    float* attn = out + (size_t)2 * 1024 * 1024;      // (2,16,2048,2048)

    __nv_bfloat16 *wHi, *wLo, *enhHi, *enhLo, *hHi, *hLo, *qHi, *qLo,
                  *kHi, *kLo, *vtHi, *vtLo, *cxHi, *cxLo;
    float* sc;
    cudaGetSymbolAddress((void**)&wHi,  g_w_hi);
    cudaGetSymbolAddress((void**)&wLo,  g_w_lo);
    cudaGetSymbolAddress((void**)&enhHi, g_enh_hi);
    cudaGetSymbolAddress((void**)&enhLo, g_enh_lo);
    cudaGetSymbolAddress((void**)&hHi,  g_h_hi);
    cudaGetSymbolAddress((void**)&hLo,  g_h_lo);
    cudaGetSymbolAddress((void**)&qHi,  g_q_hi);
    cudaGetSymbolAddress((void**)&qLo,  g_q_lo);
    cudaGetSymbolAddress((void**)&kHi,  g_k_hi);
    cudaGetSymbolAddress((void**)&kLo,  g_k_lo);
    cudaGetSymbolAddress((void**)&vtHi, g_vt_hi);
    cudaGetSymbolAddress((void**)&vtLo, g_vt_lo);
    cudaGetSymbolAddress((void**)&cxHi, g_ctx_hi);
    cudaGetSymbolAddress((void**)&cxLo, g_ctx_lo);
    cudaGetSymbolAddress((void**)&sc,   g_sc);

    const size_t MW = 1048576;
    const int SMEM3 = 3 * ((2 * 128 + 2 * 64) * 80);   // 92160
    cudaFuncSetAttribute(gemm3_mma<0>, cudaFuncAttributeMaxDynamicSharedMemorySize, SMEM3);
    cudaFuncSetAttribute(gemm3_mma<1>, cudaFuncAttributeMaxDynamicSharedMemorySize, SMEM3);
    cudaFuncSetAttribute(gemm3_mma<2>, cudaFuncAttributeMaxDynamicSharedMemorySize, SMEM3);

    // 0) convert weights + x into hi/lo bf16  (2 launches)
    conv_w_kernel<<<dim3(1024, 6), 256>>>(M1, M2, Wq, Wk, Wv, Wo, wHi, wLo);
    conv_kernel<<<2048, 256>>>(x, enhHi + 2097152, enhLo + 2097152, 524288);

    // 1) h = relu(x @ M1^T + bm1)
    gemm3_mma<0><<<dim3(16, 16), 256, SMEM3>>>(
        enhHi + 2097152, enhLo + 2097152, nullptr, wHi + 0 * MW, wLo + 0 * MW, bm1,
        nullptr, hHi, hLo, 1024, 1024, 1024, 1024, 1.0f, 1, 0, 0);
    // 2) enh[0:2048] = h @ M2^T + bm2
    gemm3_mma<0><<<dim3(16, 16), 256, SMEM3>>>(
        hHi, hLo, nullptr, wHi + 1 * MW, wLo + 1 * MW, bm2,
        nullptr, enhHi, enhLo, 1024, 1024, 1024, 1024, 1.0f, 0, 0, 0);
    // 3) Q, K, V(transposed) = enh @ W^T + b
    gemm3_mma<0><<<dim3(16, 32), 256, SMEM3>>>(
        enhHi, enhLo, nullptr, wHi + 2 * MW, wLo + 2 * MW, bq,
        nullptr, qHi, qLo, 1024, 1024, 1024, 1024, 1.0f, 0, 0, 0);
    gemm3_mma<0><<<dim3(16, 32), 256, SMEM3>>>(
        enhHi, enhLo, nullptr, wHi + 3 * MW, wLo + 3 * MW, bk,
        nullptr, kHi, kLo, 1024, 1024, 1024, 1024, 1.0f, 0, 0, 0);
    gemm3_mma<0><<<dim3(16, 32), 256, SMEM3>>>(
        enhHi, enhLo, nullptr, wHi + 4 * MW, wLo + 4 * MW, bv,
        nullptr, vtHi, vtLo, 1024, 1024, 1024, 1024, 1.0f, 0, 0, 1);

    // 4+5) per 4-head group: QK scores -> L2-hot scratch, softmax -> attn
    for (int g = 0; g < 8; ++g) {
        gemm3_mma<1><<<dim3(32, 16, 4), 256, SMEM3>>>(
            qHi, qLo, nullptr, kHi, kLo, nullptr,
            sc, nullptr, nullptr, 64, 1024, 1024, 2048, 0.125f, 0, g * 4, 0);
        softmax_kernel<<<8192, 256>>>(sc, attn, g * 4);
    }

    // 6) ctx = attn[., 1024:, :] @ V_bh  (A = fp32 attn, split in-kernel)
    gemm3_mma<2><<<dim3(1, 8, 32), 256, SMEM3>>>(
        nullptr, nullptr, attn, vtHi, vtLo, nullptr,
        nullptr, cxHi, cxLo, 2048, 2048, 2048, 1024, 1.0f, 0, 0, 0);
    // 7) out = ctx @ Wo^T + bo  (fp32)
    gemm3_mma<0><<<dim3(16, 16), 256, SMEM3>>>(
        cxHi, cxLo, nullptr, wHi + 5 * MW, wLo + 5 * MW, bo,
        out, nullptr, nullptr, 1024, 1024, 1024, 1024, 1.0f, 0, 0, 0);
}

// round 8
// speedup vs baseline: 1.0462x; 1.0462x over previous
#include <cuda_runtime.h>
#include <cuda_bf16.h>
#include <cstdint>
#include <cstddef>

// ============================================================================
// helpers (base sm_103 ISA only: ldmatrix + mma.sync + cp.async)
// ============================================================================
__device__ __forceinline__ uint32_t smem_u32(const void* p) {
    uint32_t a;
    asm("{ .reg .u64 t; cvta.to.shared.u64 t, %1; cvt.u32.u64 %0, t; }"
        : "=r"(a) : "l"(p));
    return a;
}

#define CP16(dst, src) \
    asm volatile("cp.async.cg.shared.global [%0], [%1], 16;" \
                 :: "r"(dst), "l"(src) : "memory")
#define CP_COMMIT() asm volatile("cp.async.commit_group;" ::: "memory")
#define CP_WAIT1()  asm volatile("cp.async.wait_group 1;" ::: "memory")
#define CP_WAIT0()  asm volatile("cp.async.wait_group 0;" ::: "memory")

#define LDSM4(r, addr) \
    asm volatile("ldmatrix.sync.aligned.m8n8.x4.shared.b16 {%0,%1,%2,%3}, [%4];" \
                 : "=r"((r)[0]), "=r"((r)[1]), "=r"((r)[2]), "=r"((r)[3]) : "r"(addr))

#define MMA16816(d, a, b0, b1) \
    asm volatile("mma.sync.aligned.m16n8k16.row.col.f32.bf16.bf16.f32 " \
                 "{%0,%1,%2,%3},{%4,%5,%6,%7},{%8,%9},{%0,%1,%2,%3};" \
                 : "+f"((d)[0]), "+f"((d)[1]), "+f"((d)[2]), "+f"((d)[3]) \
                 : "r"((a)[0]), "r"((a)[1]), "r"((a)[2]), "r"((a)[3]), \
                   "r"(b0), "r"(b1))

#define STS128U(addr, r) \
    asm volatile("st.shared.v4.b32 [%0], {%1, %2, %3, %4};" \
                 :: "r"(addr), "r"((r)[0]), "r"((r)[1]), "r"((r)[2]), "r"((r)[3]) : "memory")

__device__ __forceinline__ uint32_t packbf2(float f0, float f1) {
    __nv_bfloat162 t(__float2bfloat16(f0), __float2bfloat16(f1));
    return *reinterpret_cast<uint32_t*>(&t);
}

// ============================================================================
// Scratch (device globals; no allocations allowed)
// ============================================================================
__device__ __align__(16) __nv_bfloat16 g_w_hi[6 * 1048576];   // [M1,M2,Wq,Wk,Wv,Wo]
__device__ __align__(16) __nv_bfloat16 g_w_lo[6 * 1048576];
__device__ __align__(16) __nv_bfloat16 g_enh_hi[4194304], g_enh_lo[4194304]; // [mem;x]
__device__ __align__(16) __nv_bfloat16 g_h_hi[2097152],  g_h_lo[2097152];
__device__ __align__(16) __nv_bfloat16 g_q_hi[4194304],  g_q_lo[4194304];
__device__ __align__(16) __nv_bfloat16 g_k_hi[4194304],  g_k_lo[4194304];
__device__ __align__(16) __nv_bfloat16 g_vt_hi[4194304], g_vt_lo[4194304];   // [32][64][2048]
__device__ __align__(16) __nv_bfloat16 g_ctx_hi[2097152], g_ctx_lo[2097152];
__device__ __align__(16) float g_sc[16777216];   // 67 MB: raw scores for 4 heads (L2-hot)

// ============================================================================
// fp32 -> (bf16 hi, bf16 lo) conversions
// ============================================================================
__global__ void __launch_bounds__(256) conv_w_kernel(
    const float* __restrict__ s0, const float* __restrict__ s1,
    const float* __restrict__ s2, const float* __restrict__ s3,
    const float* __restrict__ s4, const float* __restrict__ s5,
    __nv_bfloat16* __restrict__ hi, __nv_bfloat16* __restrict__ lo)
{
    const int w = blockIdx.y;
    const float* src = (w == 0) ? s0 : (w == 1) ? s1 : (w == 2) ? s2
                    : (w == 3) ? s3 : (w == 4) ? s4 : s5;
    hi += (size_t)w * 1048576;
    lo += (size_t)w * 1048576;
    int i = blockIdx.x * 256 + threadIdx.x;           // n4 = 262144
    float4 v = reinterpret_cast<const float4*>(src)[i];
    float vals[4] = {v.x, v.y, v.z, v.w};
    __nv_bfloat16 h[4], l[4];
#pragma unroll
    for (int j = 0; j < 4; ++j) {
        h[j] = __float2bfloat16(vals[j]);
        l[j] = __float2bfloat16(vals[j] - __bfloat162float(h[j]));
    }
    reinterpret_cast<__nv_bfloat162*>(hi)[2 * i]     = {h[0], h[1]};
    reinterpret_cast<__nv_bfloat162*>(hi)[2 * i + 1] = {h[2], h[3]};
    reinterpret_cast<__nv_bfloat162*>(lo)[2 * i]     = {l[0], l[1]};
    reinterpret_cast<__nv_bfloat162*>(lo)[2 * i + 1] = {l[2], l[3]};
}

__global__ void __launch_bounds__(256) conv_kernel(
    const float* __restrict__ src, __nv_bfloat16* __restrict__ hi,
    __nv_bfloat16* __restrict__ lo, int n4)
{
    int i = blockIdx.x * 256 + threadIdx.x;
    if (i >= n4) return;
    float4 v = reinterpret_cast<const float4*>(src)[i];
    float vals[4] = {v.x, v.y, v.z, v.w};
    __nv_bfloat16 h[4], l[4];
#pragma unroll
    for (int j = 0; j < 4; ++j) {
        h[j] = __float2bfloat16(vals[j]);
        l[j] = __float2bfloat16(vals[j] - __bfloat162float(h[j]));
    }
    reinterpret_cast<__nv_bfloat162*>(hi)[2 * i]     = {h[0], h[1]};
    reinterpret_cast<__nv_bfloat162*>(hi)[2 * i + 1] = {h[2], h[3]};
    reinterpret_cast<__nv_bfloat162*>(lo)[2 * i]     = {l[0], l[1]};
    reinterpret_cast<__nv_bfloat162*>(lo)[2 * i + 1] = {l[2], l[3]};
}

// ============================================================================
// bf16x3 NT GEMM via mma.sync: C = act(scale*(A@B^T) + bias)
// CTA tile 256 x (2*WN), 8 warps in 4(m) x 2(n) grid, warp tile 64 x WN.
// BK=32, 3-stage cp.async pipeline, one barrier per chunk.
// 3 fused passes per chunk: Ahi*Bhi + Alo*Bhi + Ahi*Blo, fp32 reg accum.
// MODE 0: plain    MODE 1: QK (z=zbase+bz; C=scratch local z)
// MODE 2: AV       A from fp32 attn lower half (__ldcs) + in-kernel hi/lo split
// transV: scatter C into Vt[32][64][2048]
// ============================================================================
template <int WN, int MODE>
__global__ void __launch_bounds__(256, 1) gemm3_mma(
    const __nv_bfloat16* __restrict__ Ahi, const __nv_bfloat16* __restrict__ Alo,
    const float* __restrict__ Af,
    const __nv_bfloat16* __restrict__ Bhi, const __nv_bfloat16* __restrict__ Blo,
    const float* __restrict__ bias,
    float* __restrict__ Cf, __nv_bfloat16* __restrict__ Chi, __nv_bfloat16* __restrict__ Clo,
    int K, int lda, int ldb, int ldc,
    float scale, int relu, int zbase, int transV)
{
    extern __shared__ __align__(128) char smem[];
    constexpr int BN = 2 * WN;
    constexpr int NJ = WN / 8;                  // 8-col n-frags per warp
    constexpr int NB = WN / 16;                 // B LDSM4 per operand-half
    constexpr int STRIDE = 80;                  // 64B row + 16B pad
    constexpr int A_BYTES = 256 * STRIDE;       // 20480
    constexpr int B_BYTES = BN * STRIDE;
    constexpr int STAGE = 2 * A_BYTES + 2 * B_BYTES;

    const int tid = threadIdx.x;
    const int wid = tid >> 5, lid = tid & 31;
    const int m0 = blockIdx.y * 256;
    const int n0 = blockIdx.x * BN;
    const int z  = (MODE == 1) ? (zbase + blockIdx.z) : blockIdx.z;

    const int mw = wid >> 1, nw = wid & 1;
    const int r0 = mw * 64;
    const int c0 = nw * WN;

    size_t aOff = 0, bOff = 0;
    if (MODE == 1) {
        aOff = bOff = (size_t)(z >> 4) * 2097152 + (size_t)(z & 15) * 64;
    } else if (MODE == 2) {
        bOff = (size_t)z * 131072;
    }
    if (MODE != 2) { Ahi += aOff; Alo += aOff; }
    Bhi += bOff; Blo += bOff;

    const uint32_t sbase = smem_u32(smem);

    auto issueA = [&](int c) {
        const int kt = c << 5;
        const uint32_t sb = sbase + (c % 3) * STAGE;
        const int seg = tid & 3;
        const int rbase = tid >> 2;
#pragma unroll
        for (int u = 0; u < 4; ++u) {           // 256 rows x 4 segs
            int row = rbase + u * 64;
            const char* sH = (const char*)(Ahi + (size_t)(m0 + row) * lda + kt) + seg * 16;
            const char* sL = (const char*)(Alo + (size_t)(m0 + row) * lda + kt) + seg * 16;
            uint32_t d = sb + row * STRIDE + seg * 16;
            CP16(d, sH);
            CP16(d + A_BYTES, sL);
        }
    };
    auto issueB = [&](int c) {
        const int kt = c << 5;
        const uint32_t sb = sbase + (c % 3) * STAGE;
        const int seg = tid & 3;
        const int rbase = tid >> 2;
        constexpr int BU = BN / 64;
#pragma unroll
        for (int u = 0; u < BU; ++u) {
            int row = rbase + u * 64;
            const char* sH = (const char*)(Bhi + (size_t)(n0 + row) * ldb + kt) + seg * 16;
            const char* sL = (const char*)(Blo + (size_t)(n0 + row) * ldb + kt) + seg * 16;
            uint32_t d = sb + 2 * A_BYTES + row * STRIDE + seg * 16;
            CP16(d, sH);
            CP16(d + B_BYTES, sL);
        }
    };

    float acc[4][NJ][4];
#pragma unroll
    for (int i = 0; i < 4; ++i)
#pragma unroll
        for (int j = 0; j < NJ; ++j)
#pragma unroll
            for (int q = 0; q < 4; ++q) acc[i][j][q] = 0.0f;

    const uint32_t aRow = (uint32_t)(r0 + (lid & 15)) * STRIDE + ((lid >> 4) & 1) * 16;
    const uint32_t bRow = (uint32_t)(c0 + (lid & 7) + ((lid >> 4) & 1) * 8) * STRIDE
                        + ((lid >> 3) & 1) * 16;

    auto mma_chunk = [&](int c) {
        const uint32_t sb = sbase + (c % 3) * STAGE;
        const uint32_t aH = sb, aL = sb + A_BYTES;
        const uint32_t bH = sb + 2 * A_BYTES, bL = bH + B_BYTES;
#pragma unroll
        for (int s = 0; s < 2; ++s) {
            uint32_t ah[4][4], al[4][4], bb[NB][4];
#pragma unroll
            for (int mi = 0; mi < 4; ++mi)
                LDSM4(ah[mi], aH + aRow + mi * 16 * STRIDE + s * 32);
#pragma unroll
            for (int j = 0; j < NB; ++j)
                LDSM4(bb[j], bH + bRow + j * 16 * STRIDE + s * 32);
            // pass 1: Ahi * Bhi
#pragma unroll
            for (int mi = 0; mi < 4; ++mi)
#pragma unroll
                for (int nj = 0; nj < NJ; ++nj)
                    MMA16816(acc[mi][nj], ah[mi], bb[nj >> 1][(nj & 1) * 2], bb[nj >> 1][(nj & 1) * 2 + 1]);
            // pass 2: Alo * Bhi
#pragma unroll
            for (int mi = 0; mi < 4; ++mi)
                LDSM4(al[mi], aL + aRow + mi * 16 * STRIDE + s * 32);
#pragma unroll
            for (int mi = 0; mi < 4; ++mi)
#pragma unroll
                for (int nj = 0; nj < NJ; ++nj)
                    MMA16816(acc[mi][nj], al[mi], bb[nj >> 1][(nj & 1) * 2], bb[nj >> 1][(nj & 1) * 2 + 1]);
            // pass 3: Ahi * Blo
#pragma unroll
            for (int j = 0; j < NB; ++j)
                LDSM4(bb[j], bL + bRow + j * 16 * STRIDE + s * 32);
#pragma unroll
            for (int mi = 0; mi < 4; ++mi)
#pragma unroll
                for (int nj = 0; nj < NJ; ++nj)
                    MMA16816(acc[mi][nj], ah[mi], bb[nj >> 1][(nj & 1) * 2], bb[nj >> 1][(nj & 1) * 2 + 1]);
        }
    };

    const int nC = K >> 5;

    if constexpr (MODE != 2) {
        issueA(0); issueB(0); CP_COMMIT();
        if (nC > 1) { issueA(1); issueB(1); }
        CP_COMMIT();
        for (int c = 0; c < nC; ++c) {
            if (c == nC - 1) { CP_WAIT0(); } else { CP_WAIT1(); }
            __syncthreads();
            if (c + 2 < nC) { issueA(c + 2); issueB(c + 2); CP_COMMIT(); }
            mma_chunk(c);
        }
    } else {
        // A from fp32 attn (lower half): reg-staged __ldcs + convert + STS
        const float* Abase = Af + (size_t)z * 4194304 + (size_t)1024 * 2048;
        const float* Aptr = Abase + (size_t)(m0 + tid) * 2048;

        auto ldA = [&](int c, float4* r) {
            const float4* p = reinterpret_cast<const float4*>(Aptr + (c << 5));
#pragma unroll
            for (int j = 0; j < 8; ++j) r[j] = __ldcs(p + j);
        };
        auto stsA = [&](int c, const float4* r) {
            const uint32_t sb = sbase + (c % 3) * STAGE;
            const uint32_t d = sb + tid * STRIDE;
#pragma unroll
            for (int j = 0; j < 4; ++j) {       // 8 floats -> one 16B hi + 16B lo
                float f[8] = {r[2 * j].x, r[2 * j].y, r[2 * j].z, r[2 * j].w,
                              r[2 * j + 1].x, r[2 * j + 1].y, r[2 * j + 1].z, r[2 * j + 1].w};
                uint32_t hp[4], lp[4];
#pragma unroll
                for (int q = 0; q < 4; ++q) {
                    float f0 = f[2 * q], f1 = f[2 * q + 1];
                    __nv_bfloat16 h0 = __float2bfloat16(f0), h1 = __float2bfloat16(f1);
                    hp[q] = packbf2(f0, f1);
                    lp[q] = packbf2(f0 - __bfloat162float(h0), f1 - __bfloat162float(h1));
                }
                STS128U(d + j * 16, hp);
                STS128U(d + j * 16 + A_BYTES, lp);
            }
        };

        float4 Rn[8];
        ldA(0, Rn); stsA(0, Rn);
        ldA(1, Rn); stsA(1, Rn);
        issueB(0); CP_COMMIT();
        issueB(1); CP_COMMIT();
        if (nC > 2) ldA(2, Rn);
        for (int c = 0; c < nC; ++c) {
            if (c == nC - 1) { CP_WAIT0(); } else { CP_WAIT1(); }
            __syncthreads();
            if (c + 2 < nC) {
                stsA(c + 2, Rn);
                issueB(c + 2); CP_COMMIT();
                if (c + 3 < nC) ldA(c + 3, Rn);
            }
            mma_chunk(c);
        }
    }

    // ---------------- epilogue ----------------
    size_t cOffZ = 0;
    if constexpr (MODE == 1)      cOffZ = (size_t)blockIdx.z * 4194304;     // local z in scratch
    else if constexpr (MODE == 2) cOffZ = (size_t)(z >> 4) * 1048576 + (size_t)(z & 15) * 64;

    const int grp = lid >> 2, tig = lid & 3;

#pragma unroll
    for (int mi = 0; mi < 4; ++mi) {
#pragma unroll
        for (int nj = 0; nj < NJ; ++nj) {
            const int mr = m0 + r0 + mi * 16 + grp;
            const int nc = n0 + c0 + nj * 8 + tig * 2;
            float v0 = acc[mi][nj][0] * scale, v1 = acc[mi][nj][1] * scale;
            float v2 = acc[mi][nj][2] * scale, v3 = acc[mi][nj][3] * scale;
            if (bias) {
                float b0 = __ldg(bias + nc), b1 = __ldg(bias + nc + 1);
                v0 += b0; v1 += b1; v2 += b0; v3 += b1;
            }
            if (relu) {
                v0 = fmaxf(v0, 0.0f); v1 = fmaxf(v1, 0.0f);
                v2 = fmaxf(v2, 0.0f); v3 = fmaxf(v3, 0.0f);
            }
            if (Cf) {
                *reinterpret_cast<float2*>(&Cf[cOffZ + (size_t)mr * ldc + nc]) =
                    make_float2(v0, v1);
                *reinterpret_cast<float2*>(&Cf[cOffZ + (size_t)(mr + 8) * ldc + nc]) =
                    make_float2(v2, v3);
            }
            if (Chi) {
                __nv_bfloat16 h0 = __float2bfloat16(v0), h1 = __float2bfloat16(v1);
                __nv_bfloat16 h2 = __float2bfloat16(v2), h3 = __float2bfloat16(v3);
                __nv_bfloat16 l0 = __float2bfloat16(v0 - __bfloat162float(h0));
                __nv_bfloat16 l1 = __float2bfloat16(v1 - __bfloat162float(h1));
                __nv_bfloat16 l2 = __float2bfloat16(v2 - __bfloat162float(h2));
                __nv_bfloat16 l3 = __float2bfloat16(v3 - __bfloat162float(h3));
                if (!transV) {
                    size_t i0 = cOffZ + (size_t)mr * ldc + nc;
                    size_t i1 = cOffZ + (size_t)(mr + 8) * ldc + nc;
                    *reinterpret_cast<__nv_bfloat162*>(&Chi[i0]) = {h0, h1};
                    *reinterpret_cast<__nv_bfloat162*>(&Chi[i1]) = {h2, h3};
                    *reinterpret_cast<__nv_bfloat162*>(&Clo[i0]) = {l0, l1};
                    *reinterpret_cast<__nv_bfloat162*>(&Clo[i1]) = {l2, l3};
                } else {
#pragma unroll
                    for (int e = 0; e < 4; ++e) {
                        int rr = mr + (e >> 1) * 8;
                        int nn = nc + (e & 1);
                        size_t idx = ((size_t)(rr >> 11) * 16 + (size_t)(nn >> 6)) * 131072
                                   + (size_t)(nn & 63) * 2048 + (size_t)(rr & 2047);
                        __nv_bfloat16 hv = (e == 0) ? h0 : (e == 1) ? h1 : (e == 2) ? h2 : h3;
                        __nv_bfloat16 lv = (e == 0) ? l0 : (e == 1) ? l1 : (e == 2) ? l2 : l3;
                        Chi[idx] = hv;
                        Clo[idx] = lv;
                    }
                }
            }
        }
    }
}

// ============================================================================
// Row softmax: scratch (L2-hot, 4 heads) -> attn output (streaming .cs)
// ============================================================================
__global__ void __launch_bounds__(256) softmax_kernel(
    const float* __restrict__ scratch, float* __restrict__ attn, int zbase)
{
    const int zloc = blockIdx.x >> 11;
    const int rr = blockIdx.x & 2047;
    const float4* p = reinterpret_cast<const float4*>(
        scratch + (size_t)zloc * 4194304 + (size_t)rr * 2048);
    float4* q = reinterpret_cast<float4*>(
        attn + (size_t)(zbase + zloc) * 4194304 + (size_t)rr * 2048);
    const int tid = threadIdx.x;
    float4 v0 = p[tid];
    float4 v1 = p[tid + 256];

    float mx = fmaxf(fmaxf(fmaxf(v0.x, v0.y), fmaxf(v0.z, v0.w)),
                     fmaxf(fmaxf(v1.x, v1.y), fmaxf(v1.z, v1.w)));
#pragma unroll
    for (int o = 16; o; o >>= 1) mx = fmaxf(mx, __shfl_xor_sync(0xffffffffu, mx, o));

    __shared__ float smax[8], ssum[8];
    if ((tid & 31) == 0) smax[tid >> 5] = mx;
    __syncthreads();
    float m = smax[0];
#pragma unroll
    for (int i = 1; i < 8; i++) m = fmaxf(m, smax[i]);

    v0.x = __expf(v0.x - m); v0.y = __expf(v0.y - m);
    v0.z = __expf(v0.z - m); v0.w = __expf(v0.w - m);
    v1.x = __expf(v1.x - m); v1.y = __expf(v1.y - m);
    v1.z = __expf(v1.z - m); v1.w = __expf(v1.w - m);

    float s = v0.x + v0.y + v0.z + v0.w + v1.x + v1.y + v1.z + v1.w;
#pragma unroll
    for (int o = 16; o; o >>= 1) s += __shfl_xor_sync(0xffffffffu, s, o);
    if ((tid & 31) == 0) ssum[tid >> 5] = s;
    __syncthreads();
    float tot = 0.0f;
#pragma unroll
    for (int i = 0; i < 8; i++) tot += ssum[i];
    const float inv = 1.0f / tot;

    v0.x *= inv; v0.y *= inv; v0.z *= inv; v0.w *= inv;
    v1.x *= inv; v1.y *= inv; v1.z *= inv; v1.w *= inv;
    __stcs(q + tid, v0);
    __stcs(q + tid + 256, v1);
}

// ============================================================================
// Launch
// ============================================================================
extern "C" void kernel_launch(void* const* d_in, const int* in_sizes, int n_in,
                              void* d_out, int out_size)
{
    const float* x   = (const float*)d_in[0];
    const float* Wq  = (const float*)d_in[1];
    const float* bq  = (const float*)d_in[2];
    const float* Wk  = (const float*)d_in[3];
    const float* bk  = (const float*)d_in[4];
    const float* Wv  = (const float*)d_in[5];
    const float* bv  = (const float*)d_in[6];
    const float* Wo  = (const float*)d_in[7];
    const float* bo  = (const float*)d_in[8];
    const float* M1  = (const float*)d_in[9];
    const float* bm1 = (const float*)d_in[10];
    const float* M2  = (const float*)d_in[11];
    const float* bm2 = (const float*)d_in[12];

    float* out  = (float*)d_out;                      // (2,1024,1024)
    float* attn = out + (size_t)2 * 1024 * 1024;      // (2,16,2048,2048)

    __nv_bfloat16 *wHi, *wLo, *enhHi, *enhLo, *hHi, *hLo, *qHi, *qLo,
                  *kHi, *kLo, *vtHi, *vtLo, *cxHi, *cxLo;
    float* sc;
    cudaGetSymbolAddress((void**)&wHi,  g_w_hi);
    cudaGetSymbolAddress((void**)&wLo,  g_w_lo);
    cudaGetSymbolAddress((void**)&enhHi, g_enh_hi);
    cudaGetSymbolAddress((void**)&enhLo, g_enh_lo);
    cudaGetSymbolAddress((void**)&hHi,  g_h_hi);
    cudaGetSymbolAddress((void**)&hLo,  g_h_lo);
    cudaGetSymbolAddress((void**)&qHi,  g_q_hi);
    cudaGetSymbolAddress((void**)&qLo,  g_q_lo);
    cudaGetSymbolAddress((void**)&kHi,  g_k_hi);
    cudaGetSymbolAddress((void**)&kLo,  g_k_lo);
    cudaGetSymbolAddress((void**)&vtHi, g_vt_hi);
    cudaGetSymbolAddress((void**)&vtLo, g_vt_lo);
    cudaGetSymbolAddress((void**)&cxHi, g_ctx_hi);
    cudaGetSymbolAddress((void**)&cxLo, g_ctx_lo);
    cudaGetSymbolAddress((void**)&sc,   g_sc);

    const size_t MW = 1048576;
    // stages: 2*A(20480) + 2*B(BN*80)
    const int SMEM_BN128 = 3 * (2 * 20480 + 2 * 128 * 80);  // 184320
    const int SMEM_BN64  = 3 * (2 * 20480 + 2 * 64 * 80);   // 153600
    cudaFuncSetAttribute(gemm3_mma<32, 0>, cudaFuncAttributeMaxDynamicSharedMemorySize, SMEM_BN64);
    cudaFuncSetAttribute(gemm3_mma<64, 0>, cudaFuncAttributeMaxDynamicSharedMemorySize, SMEM_BN128);
    cudaFuncSetAttribute(gemm3_mma<64, 1>, cudaFuncAttributeMaxDynamicSharedMemorySize, SMEM_BN128);
    cudaFuncSetAttribute(gemm3_mma<32, 2>, cudaFuncAttributeMaxDynamicSharedMemorySize, SMEM_BN64);

    // 0) convert weights + x into hi/lo bf16  (2 launches)
    conv_w_kernel<<<dim3(1024, 6), 256>>>(M1, M2, Wq, Wk, Wv, Wo, wHi, wLo);
    conv_kernel<<<2048, 256>>>(x, enhHi + 2097152, enhLo + 2097152, 524288);

    // 1) h = relu(x @ M1^T + bm1)   [2048x1024] tile 256x64 -> grid 128
    gemm3_mma<32, 0><<<dim3(16, 8), 256, SMEM_BN64>>>(
        enhHi + 2097152, enhLo + 2097152, nullptr, wHi + 0 * MW, wLo + 0 * MW, bm1,
        nullptr, hHi, hLo, 1024, 1024, 1024, 1024, 1.0f, 1, 0, 0);
    // 2) enh[0:2048] = h @ M2^T + bm2
    gemm3_mma<32, 0><<<dim3(16, 8), 256, SMEM_BN64>>>(
        hHi, hLo, nullptr, wHi + 1 * MW, wLo + 1 * MW, bm2,
        nullptr, enhHi, enhLo, 1024, 1024, 1024, 1024, 1.0f, 0, 0, 0);
    // 3) Q, K, V(transposed) = enh @ W^T + b   [4096x1024] tile 256x128 -> grid 128
    gemm3_mma<64, 0><<<dim3(8, 16), 256, SMEM_BN128>>>(
        enhHi, enhLo, nullptr, wHi + 2 * MW, wLo + 2 * MW, bq,
        nullptr, qHi, qLo, 1024, 1024, 1024, 1024, 1.0f, 0, 0, 0);
    gemm3_mma<64, 0><<<dim3(8, 16), 256, SMEM_BN128>>>(
        enhHi, enhLo, nullptr, wHi + 3 * MW, wLo + 3 * MW, bk,
        nullptr, kHi, kLo, 1024, 1024, 1024, 1024, 1.0f, 0, 0, 0);
    gemm3_mma<64, 0><<<dim3(8, 16), 256, SMEM_BN128>>>(
        enhHi, enhLo, nullptr, wHi + 4 * MW, wLo + 4 * MW, bv,
        nullptr, vtHi, vtLo, 1024, 1024, 1024, 1024, 1.0f, 0, 0, 1);

    // 4+5) per 4-head group: QK scores -> L2-hot scratch, softmax -> attn
    for (int g = 0; g < 8; ++g) {
        gemm3_mma<64, 1><<<dim3(16, 8, 4), 256, SMEM_BN128>>>(
            qHi, qLo, nullptr, kHi, kLo, nullptr,
            sc, nullptr, nullptr, 64, 1024, 1024, 2048, 0.125f, 0, g * 4, 0);
        softmax_kernel<<<8192, 256>>>(sc, attn, g * 4);
    }

    // 6) ctx = attn[., 1024:, :] @ V_bh   tile 256x64 -> grid 128
    gemm3_mma<32, 2><<<dim3(1, 4, 32), 256, SMEM_BN64>>>(
        nullptr, nullptr, attn, vtHi, vtLo, nullptr,
        nullptr, cxHi, cxLo, 2048, 2048, 2048, 1024, 1.0f, 0, 0, 0);
    // 7) out = ctx @ Wo^T + bo   [2048x1024] tile 256x64 -> grid 128
    gemm3_mma<32, 0><<<dim3(16, 8), 256, SMEM_BN64>>>(
        cxHi, cxLo, nullptr, wHi + 5 * MW, wLo + 5 * MW, bo,
        out, nullptr, nullptr, 1024, 1024, 1024, 1024, 1.0f, 0, 0, 0);
}

// round 12
// speedup vs baseline: 1.4141x; 1.3517x over previous
#include <cuda_runtime.h>
#include <cuda_fp16.h>
#include <cstdint>
#include <cstddef>

// ============================================================================
// helpers (base sm_103 ISA only: ldmatrix + mma.sync + cp.async)
// ============================================================================
__device__ __forceinline__ uint32_t smem_u32(const void* p) {
    uint32_t a;
    asm("{ .reg .u64 t; cvta.to.shared.u64 t, %1; cvt.u32.u64 %0, t; }"
        : "=r"(a) : "l"(p));
    return a;
}

#define CP16(dst, src) \
    asm volatile("cp.async.cg.shared.global [%0], [%1], 16;" \
                 :: "r"(dst), "l"(src) : "memory")
#define CP_COMMIT() asm volatile("cp.async.commit_group;" ::: "memory")
#define CP_WAIT1()  asm volatile("cp.async.wait_group 1;" ::: "memory")
#define CP_WAIT0()  asm volatile("cp.async.wait_group 0;" ::: "memory")

#define LDSM4(r, addr) \
    asm volatile("ldmatrix.sync.aligned.m8n8.x4.shared.b16 {%0,%1,%2,%3}, [%4];" \
                 : "=r"((r)[0]), "=r"((r)[1]), "=r"((r)[2]), "=r"((r)[3]) : "r"(addr))

#define MMA16816(d, a, b0, b1) \
    asm volatile("mma.sync.aligned.m16n8k16.row.col.f32.f16.f16.f32 " \
                 "{%0,%1,%2,%3},{%4,%5,%6,%7},{%8,%9},{%0,%1,%2,%3};" \
                 : "+f"((d)[0]), "+f"((d)[1]), "+f"((d)[2]), "+f"((d)[3]) \
                 : "r"((a)[0]), "r"((a)[1]), "r"((a)[2]), "r"((a)[3]), \
                   "r"(b0), "r"(b1))

#define STS128U(addr, r) \
    asm volatile("st.shared.v4.b32 [%0], {%1, %2, %3, %4};" \
                 :: "r"(addr), "r"((r)[0]), "r"((r)[1]), "r"((r)[2]), "r"((r)[3]) : "memory")

__device__ __forceinline__ uint32_t packh2(float f0, float f1) {
    __half2 t = __halves2half2(__float2half_rn(f0), __float2half_rn(f1));
    return *reinterpret_cast<uint32_t*>(&t);
}

// ============================================================================
// Scratch (device globals; no allocations allowed)
// ============================================================================
__device__ __align__(16) __half g_w_h[6 * 1048576];      // [M1,M2,Wq,Wk,Wv,Wo] fp16
__device__ __align__(16) __half g_enh_hi[4194304], g_enh_lo[4194304];  // [mem;x]
__device__ __align__(16) __half g_h_hi[2097152],  g_h_lo[2097152];
__device__ __align__(16) __half g_q_hi[4194304],  g_q_lo[4194304];
__device__ __align__(16) __half g_k_h[4194304];          // K: B operand, single fp16
__device__ __align__(16) __half g_vt_h[4194304];         // V^T [32][64][2048], single
__device__ __align__(16) __half g_ctx_hi[2097152], g_ctx_lo[2097152];
__device__ __align__(16) float g_sc[16777216];   // 67 MB: raw scores, 4 heads (L2-hot)

// ============================================================================
// fp32 -> fp16 conversions
// ============================================================================
__global__ void __launch_bounds__(256) conv_w_kernel(
    const float* __restrict__ s0, const float* __restrict__ s1,
    const float* __restrict__ s2, const float* __restrict__ s3,
    const float* __restrict__ s4, const float* __restrict__ s5,
    __half* __restrict__ hi)
{
    const int w = blockIdx.y;
    const float* src = (w == 0) ? s0 : (w == 1) ? s1 : (w == 2) ? s2
                    : (w == 3) ? s3 : (w == 4) ? s4 : s5;
    hi += (size_t)w * 1048576;
    int i = blockIdx.x * 256 + threadIdx.x;           // n4 = 262144
    float4 v = reinterpret_cast<const float4*>(src)[i];
    reinterpret_cast<__half2*>(hi)[2 * i]     = __halves2half2(__float2half_rn(v.x), __float2half_rn(v.y));
    reinterpret_cast<__half2*>(hi)[2 * i + 1] = __halves2half2(__float2half_rn(v.z), __float2half_rn(v.w));
}

__global__ void __launch_bounds__(256) conv_kernel(
    const float* __restrict__ src, __half* __restrict__ hi,
    __half* __restrict__ lo, int n4)
{
    int i = blockIdx.x * 256 + threadIdx.x;
    if (i >= n4) return;
    float4 v = reinterpret_cast<const float4*>(src)[i];
    float vals[4] = {v.x, v.y, v.z, v.w};
    __half h[4], l[4];
#pragma unroll
    for (int j = 0; j < 4; ++j) {
        h[j] = __float2half_rn(vals[j]);
        l[j] = __float2half_rn(vals[j] - __half2float(h[j]));
    }
    reinterpret_cast<__half2*>(hi)[2 * i]     = __halves2half2(h[0], h[1]);
    reinterpret_cast<__half2*>(hi)[2 * i + 1] = __halves2half2(h[2], h[3]);
    reinterpret_cast<__half2*>(lo)[2 * i]     = __halves2half2(l[0], l[1]);
    reinterpret_cast<__half2*>(lo)[2 * i + 1] = __halves2half2(l[2], l[3]);
}

// ============================================================================
// fp16x2 NT GEMM via mma.sync: C = act(scale*(A@B^T) + bias)
// A split hi/lo fp16 (2 passes: Ahi*B + Alo*B); B single fp16.
// CTA tile 128 x BN (BN=128 or 64), 8 warps, BK=32, 2-stage cp.async pipeline.
// MODE 0: plain    MODE 1: QK (z=zbase+bz; C=scratch local z)
// MODE 2: AV       A from fp32 attn lower half (__ldcs) + in-kernel hi/lo split
// transV: scatter C into Vt[32][64][2048]
// ============================================================================
template <int BN, int MODE>
__global__ void __launch_bounds__(256, 2) gemm2_mma(
    const __half* __restrict__ Ahi, const __half* __restrict__ Alo,
    const float* __restrict__ Af,
    const __half* __restrict__ Bh,
    const float* __restrict__ bias,
    float* __restrict__ Cf, __half* __restrict__ Chi, __half* __restrict__ Clo,
    int K, int lda, int ldb, int ldc,
    float scale, int relu, int zbase, int transV)
{
    extern __shared__ __align__(128) char smem[];
    constexpr int STRIDE = 80;                  // 64B row + 16B pad
    constexpr int A_BYTES = 128 * STRIDE;       // 10240
    constexpr int B_BYTES = BN * STRIDE;
    constexpr int STAGE = 2 * A_BYTES + B_BYTES;
    constexpr int WM = (BN == 128) ? 2 : 1;

    const int tid = threadIdx.x;
    const int wid = tid >> 5, lid = tid & 31;
    const int m0 = blockIdx.y * 128;
    const int n0 = blockIdx.x * BN;
    const int z  = (MODE == 1) ? (zbase + blockIdx.z) : blockIdx.z;

    const int r0 = (BN == 128) ? ((wid >> 1) * 32) : (wid * 16);
    const int c0 = (BN == 128) ? ((wid & 1) * 64) : 0;

    size_t aOff = 0, bOff = 0;
    if (MODE == 1) {
        aOff = bOff = (size_t)(z >> 4) * 2097152 + (size_t)(z & 15) * 64;
    } else if (MODE == 2) {
        bOff = (size_t)z * 131072;
    }
    if (MODE != 2) { Ahi += aOff; Alo += aOff; }
    Bh += bOff;

    const uint32_t sbase = smem_u32(smem);

    auto issueA = [&](int c) {
        const int kt = c << 5;
        const uint32_t sb = sbase + (c & 1) * STAGE;
#pragma unroll
        for (int u = 0; u < 2; ++u) {
            int id = tid + u * 256;
            int row = id >> 2, seg = id & 3;
            const char* sH = (const char*)(Ahi + (size_t)(m0 + row) * lda + kt) + seg * 16;
            const char* sL = (const char*)(Alo + (size_t)(m0 + row) * lda + kt) + seg * 16;
            uint32_t d = sb + row * STRIDE + seg * 16;
            CP16(d, sH);
            CP16(d + A_BYTES, sL);
        }
    };
    auto issueB = [&](int c) {
        const int kt = c << 5;
        const uint32_t sb = sbase + (c & 1) * STAGE;
        constexpr int BU = (BN * 4) / 256;
#pragma unroll
        for (int u = 0; u < BU; ++u) {
            int id = tid + u * 256;
            int row = id >> 2, seg = id & 3;
            const char* sH = (const char*)(Bh + (size_t)(n0 + row) * ldb + kt) + seg * 16;
            uint32_t d = sb + 2 * A_BYTES + row * STRIDE + seg * 16;
            CP16(d, sH);
        }
    };

    float acc[WM][8][4];
#pragma unroll
    for (int i = 0; i < WM; ++i)
#pragma unroll
        for (int j = 0; j < 8; ++j)
#pragma unroll
            for (int q = 0; q < 4; ++q) acc[i][j][q] = 0.0f;

    const uint32_t aRow = (uint32_t)(r0 + (lid & 15)) * STRIDE + ((lid >> 4) & 1) * 16;
    const uint32_t bRow = (uint32_t)(c0 + (lid & 7) + ((lid >> 4) & 1) * 8) * STRIDE
                        + ((lid >> 3) & 1) * 16;

    auto mma_chunk = [&](int c) {
        const uint32_t sb = sbase + (c & 1) * STAGE;
        const uint32_t aH = sb, aL = sb + A_BYTES;
        const uint32_t bB = sb + 2 * A_BYTES;
#pragma unroll
        for (int s = 0; s < 2; ++s) {
            uint32_t ah[WM][4], al[WM][4], bb[4][4];
#pragma unroll
            for (int i = 0; i < WM; ++i) {
                LDSM4(ah[i], aH + aRow + i * 16 * STRIDE + s * 32);
                LDSM4(al[i], aL + aRow + i * 16 * STRIDE + s * 32);
            }
#pragma unroll
            for (int j = 0; j < 4; ++j)
                LDSM4(bb[j], bB + bRow + j * 16 * STRIDE + s * 32);
            // pass 1: Ahi*B ; pass 2: Alo*B
#pragma unroll
            for (int i = 0; i < WM; ++i)
#pragma unroll
                for (int jt = 0; jt < 8; ++jt) {
                    MMA16816(acc[i][jt], ah[i], bb[jt >> 1][(jt & 1) * 2], bb[jt >> 1][(jt & 1) * 2 + 1]);
                    MMA16816(acc[i][jt], al[i], bb[jt >> 1][(jt & 1) * 2], bb[jt >> 1][(jt & 1) * 2 + 1]);
                }
        }
    };

    const int nC = K >> 5;

    if constexpr (MODE != 2) {
        issueA(0); issueB(0); CP_COMMIT();
        for (int c = 0; c < nC; ++c) {
            if (c + 1 < nC) { issueA(c + 1); issueB(c + 1); CP_COMMIT(); CP_WAIT1(); }
            else            { CP_WAIT0(); }
            __syncthreads();
            mma_chunk(c);
            __syncthreads();
        }
    } else {
        // A from fp32 attn (lower half): reg-staged __ldcs + convert + STS
        const float* Abase = Af + (size_t)z * 4194304 + (size_t)1024 * 2048;
        const int arow = tid >> 1, acol = (tid & 1) * 16;
        const float* Aptr = Abase + (size_t)(m0 + arow) * 2048 + acol;

        auto ldA = [&](int c, float4* r) {
            const float4* p = reinterpret_cast<const float4*>(Aptr + (c << 5));
#pragma unroll
            for (int j = 0; j < 4; ++j) r[j] = __ldcs(p + j);
        };
        auto stsA = [&](int c, const float4* r) {
            const uint32_t sb = sbase + (c & 1) * STAGE;
            const uint32_t d = sb + arow * STRIDE + acol * 2;
#pragma unroll
            for (int half = 0; half < 2; ++half) {
                float f[8] = {r[2 * half].x, r[2 * half].y, r[2 * half].z, r[2 * half].w,
                              r[2 * half + 1].x, r[2 * half + 1].y,
                              r[2 * half + 1].z, r[2 * half + 1].w};
                uint32_t hp[4], lp[4];
#pragma unroll
                for (int q = 0; q < 4; ++q) {
                    float f0 = f[2 * q], f1 = f[2 * q + 1];
                    __half h0 = __float2half_rn(f0), h1 = __float2half_rn(f1);
                    hp[q] = packh2(f0, f1);
                    lp[q] = packh2(f0 - __half2float(h0), f1 - __half2float(h1));
                }
                STS128U(d + half * 16, hp);
                STS128U(d + half * 16 + A_BYTES, lp);
            }
        };

        float4 cur[4], nxt[4];
        ldA(0, cur);
        issueB(0); CP_COMMIT();
        for (int c = 0; c < nC; ++c) {
            stsA(c, cur);
            if (c + 1 < nC) { ldA(c + 1, nxt); issueB(c + 1); CP_COMMIT(); CP_WAIT1(); }
            else            { CP_WAIT0(); }
            __syncthreads();
            mma_chunk(c);
            __syncthreads();
#pragma unroll
            for (int j = 0; j < 4; ++j) cur[j] = nxt[j];
        }
    }

    // ---------------- epilogue ----------------
    size_t cOffZ = 0;
    if constexpr (MODE == 1)      cOffZ = (size_t)blockIdx.z * 4194304;     // local z in scratch
    else if constexpr (MODE == 2) cOffZ = (size_t)(z >> 4) * 1048576 + (size_t)(z & 15) * 64;

    const int grp = lid >> 2, tig = lid & 3;

#pragma unroll
    for (int i = 0; i < WM; ++i) {
#pragma unroll
        for (int jt = 0; jt < 8; ++jt) {
            const int mr = m0 + r0 + i * 16 + grp;
            const int nc = n0 + c0 + jt * 8 + tig * 2;
            float v0 = acc[i][jt][0] * scale, v1 = acc[i][jt][1] * scale;
            float v2 = acc[i][jt][2] * scale, v3 = acc[i][jt][3] * scale;
            if (bias) {
                float b0 = __ldg(bias + nc), b1 = __ldg(bias + nc + 1);
                v0 += b0; v1 += b1; v2 += b0; v3 += b1;
            }
            if (relu) {
                v0 = fmaxf(v0, 0.0f); v1 = fmaxf(v1, 0.0f);
                v2 = fmaxf(v2, 0.0f); v3 = fmaxf(v3, 0.0f);
            }
            if (Cf) {
                *reinterpret_cast<float2*>(&Cf[cOffZ + (size_t)mr * ldc + nc]) =
                    make_float2(v0, v1);
                *reinterpret_cast<float2*>(&Cf[cOffZ + (size_t)(mr + 8) * ldc + nc]) =
                    make_float2(v2, v3);
            }
            if (Chi) {
                __half h0 = __float2half_rn(v0), h1 = __float2half_rn(v1);
                __half h2 = __float2half_rn(v2), h3 = __float2half_rn(v3);
                if (!transV) {
                    size_t i0 = cOffZ + (size_t)mr * ldc + nc;
                    size_t i1 = cOffZ + (size_t)(mr + 8) * ldc + nc;
                    *reinterpret_cast<__half2*>(&Chi[i0]) = __halves2half2(h0, h1);
                    *reinterpret_cast<__half2*>(&Chi[i1]) = __halves2half2(h2, h3);
                    if (Clo) {
                        __half l0 = __float2half_rn(v0 - __half2float(h0));
                        __half l1 = __float2half_rn(v1 - __half2float(h1));
                        __half l2 = __float2half_rn(v2 - __half2float(h2));
                        __half l3 = __float2half_rn(v3 - __half2float(h3));
                        *reinterpret_cast<__half2*>(&Clo[i0]) = __halves2half2(l0, l1);
                        *reinterpret_cast<__half2*>(&Clo[i1]) = __halves2half2(l2, l3);
                    }
                } else {
#pragma unroll
                    for (int e = 0; e < 4; ++e) {
                        int rr = mr + (e >> 1) * 8;
                        int nn = nc + (e & 1);
                        size_t idx = ((size_t)(rr >> 11) * 16 + (size_t)(nn >> 6)) * 131072
                                   + (size_t)(nn & 63) * 2048 + (size_t)(rr & 2047);
                        __half hv = (e == 0) ? h0 : (e == 1) ? h1 : (e == 2) ? h2 : h3;
                        Chi[idx] = hv;
                    }
                }
            }
        }
    }
}

// ============================================================================
// Row softmax: scratch (L2-hot, 4 heads) -> attn output (streaming .cs)
// ============================================================================
__global__ void __launch_bounds__(256) softmax_kernel(
    const float* __restrict__ scratch, float* __restrict__ attn, int zbase)
{
    const int zloc = blockIdx.x >> 11;
    const int rr = blockIdx.x & 2047;
    const float4* p = reinterpret_cast<const float4*>(
        scratch + (size_t)zloc * 4194304 + (size_t)rr * 2048);
    float4* q = reinterpret_cast<float4*>(
        attn + (size_t)(zbase + zloc) * 4194304 + (size_t)rr * 2048);
    const int tid = threadIdx.x;
    float4 v0 = p[tid];
    float4 v1 = p[tid + 256];

    float mx = fmaxf(fmaxf(fmaxf(v0.x, v0.y), fmaxf(v0.z, v0.w)),
                     fmaxf(fmaxf(v1.x, v1.y), fmaxf(v1.z, v1.w)));
#pragma unroll
    for (int o = 16; o; o >>= 1) mx = fmaxf(mx, __shfl_xor_sync(0xffffffffu, mx, o));

    __shared__ float smax[8], ssum[8];
    if ((tid & 31) == 0) smax[tid >> 5] = mx;
    __syncthreads();
    float m = smax[0];
#pragma unroll
    for (int i = 1; i < 8; i++) m = fmaxf(m, smax[i]);

    v0.x = __expf(v0.x - m); v0.y = __expf(v0.y - m);
    v0.z = __expf(v0.z - m); v0.w = __expf(v0.w - m);
    v1.x = __expf(v1.x - m); v1.y = __expf(v1.y - m);
    v1.z = __expf(v1.z - m); v1.w = __expf(v1.w - m);

    float s = v0.x + v0.y + v0.z + v0.w + v1.x + v1.y + v1.z + v1.w;
#pragma unroll
    for (int o = 16; o; o >>= 1) s += __shfl_xor_sync(0xffffffffu, s, o);
    if ((tid & 31) == 0) ssum[tid >> 5] = s;
    __syncthreads();
    float tot = 0.0f;
#pragma unroll
    for (int i = 0; i < 8; i++) tot += ssum[i];
    const float inv = 1.0f / tot;

    v0.x *= inv; v0.y *= inv; v0.z *= inv; v0.w *= inv;
    v1.x *= inv; v1.y *= inv; v1.z *= inv; v1.w *= inv;
    __stcs(q + tid, v0);
    __stcs(q + tid + 256, v1);
}

// ============================================================================
// Launch
// ============================================================================
extern "C" void kernel_launch(void* const* d_in, const int* in_sizes, int n_in,
                              void* d_out, int out_size)
{
    const float* x   = (const float*)d_in[0];
    const float* Wq  = (const float*)d_in[1];
    const float* bq  = (const float*)d_in[2];
    const float* Wk  = (const float*)d_in[3];
    const float* bk  = (const float*)d_in[4];
    const float* Wv  = (const float*)d_in[5];
    const float* bv  = (const float*)d_in[6];
    const float* Wo  = (const float*)d_in[7];
    const float* bo  = (const float*)d_in[8];
    const float* M1  = (const float*)d_in[9];
    const float* bm1 = (const float*)d_in[10];
    const float* M2  = (const float*)d_in[11];
    const float* bm2 = (const float*)d_in[12];

    float* out  = (float*)d_out;                      // (2,1024,1024)
    float* attn = out + (size_t)2 * 1024 * 1024;      // (2,16,2048,2048)

    __half *wH, *enhHi, *enhLo, *hHi, *hLo, *qHi, *qLo, *kH, *vtH, *cxHi, *cxLo;
    float* sc;
    cudaGetSymbolAddress((void**)&wH,   g_w_h);
    cudaGetSymbolAddress((void**)&enhHi, g_enh_hi);
    cudaGetSymbolAddress((void**)&enhLo, g_enh_lo);
    cudaGetSymbolAddress((void**)&hHi,  g_h_hi);
    cudaGetSymbolAddress((void**)&hLo,  g_h_lo);
    cudaGetSymbolAddress((void**)&qHi,  g_q_hi);
    cudaGetSymbolAddress((void**)&qLo,  g_q_lo);
    cudaGetSymbolAddress((void**)&kH,   g_k_h);
    cudaGetSymbolAddress((void**)&vtH,  g_vt_h);
    cudaGetSymbolAddress((void**)&cxHi, g_ctx_hi);
    cudaGetSymbolAddress((void**)&cxLo, g_ctx_lo);
    cudaGetSymbolAddress((void**)&sc,   g_sc);

    const size_t MW = 1048576;
    const int SMEM128 = 2 * (2 * 10240 + 128 * 80);   // 61440
    const int SMEM64  = 2 * (2 * 10240 + 64 * 80);    // 51200
    cudaFuncSetAttribute(gemm2_mma<128, 0>, cudaFuncAttributeMaxDynamicSharedMemorySize, SMEM128);
    cudaFuncSetAttribute(gemm2_mma<128, 1>, cudaFuncAttributeMaxDynamicSharedMemorySize, SMEM128);
    cudaFuncSetAttribute(gemm2_mma<64, 2>,  cudaFuncAttributeMaxDynamicSharedMemorySize, SMEM64);

    // 0) convert weights (single fp16) + x (hi/lo fp16)
    conv_w_kernel<<<dim3(1024, 6), 256>>>(M1, M2, Wq, Wk, Wv, Wo, wH);
    conv_kernel<<<2048, 256>>>(x, enhHi + 2097152, enhLo + 2097152, 524288);

    // 1) h = relu(x @ M1^T + bm1)
    gemm2_mma<128, 0><<<dim3(8, 16), 256, SMEM128>>>(
        enhHi + 2097152, enhLo + 2097152, nullptr, wH + 0 * MW, bm1,
        nullptr, hHi, hLo, 1024, 1024, 1024, 1024, 1.0f, 1, 0, 0);
    // 2) enh[0:2048] = h @ M2^T + bm2
    gemm2_mma<128, 0><<<dim3(8, 16), 256, SMEM128>>>(
        hHi, hLo, nullptr, wH + 1 * MW, bm2,
        nullptr, enhHi, enhLo, 1024, 1024, 1024, 1024, 1.0f, 0, 0, 0);
    // 3) Q (hi/lo), K (single), V (single, transposed)
    gemm2_mma<128, 0><<<dim3(8, 32), 256, SMEM128>>>(
        enhHi, enhLo, nullptr, wH + 2 * MW, bq,
        nullptr, qHi, qLo, 1024, 1024, 1024, 1024, 1.0f, 0, 0, 0);
    gemm2_mma<128, 0><<<dim3(8, 32), 256, SMEM128>>>(
        enhHi, enhLo, nullptr, wH + 3 * MW, bk,
        nullptr, kH, nullptr, 1024, 1024, 1024, 1024, 1.0f, 0, 0, 0);
    gemm2_mma<128, 0><<<dim3(8, 32), 256, SMEM128>>>(
        enhHi, enhLo, nullptr, wH + 4 * MW, bv,
        nullptr, vtH, nullptr, 1024, 1024, 1024, 1024, 1.0f, 0, 0, 1);

    // 4+5) per 4-head group: QK scores -> L2-hot scratch, softmax -> attn
    for (int g = 0; g < 8; ++g) {
        gemm2_mma<128, 1><<<dim3(16, 16, 4), 256, SMEM128>>>(
            qHi, qLo, nullptr, kH, nullptr,
            sc, nullptr, nullptr, 64, 1024, 1024, 2048, 0.125f, 0, g * 4, 0);
        softmax_kernel<<<8192, 256>>>(sc, attn, g * 4);
    }

    // 6) ctx = attn[., 1024:, :] @ V_bh  (A = fp32 attn, split in-kernel)
    gemm2_mma<64, 2><<<dim3(1, 8, 32), 256, SMEM64>>>(
        nullptr, nullptr, attn, vtH, nullptr,
        nullptr, cxHi, cxLo, 2048, 2048, 2048, 1024, 1.0f, 0, 0, 0);
    // 7) out = ctx @ Wo^T + bo  (fp32)
    gemm2_mma<128, 0><<<dim3(8, 16), 256, SMEM128>>>(
        cxHi, cxLo, nullptr, wH + 5 * MW, bo,
        out, nullptr, nullptr, 1024, 1024, 1024, 1024, 1.0f, 0, 0, 0);
}

// round 13
// speedup vs baseline: 1.5988x; 1.1306x over previous
#include <cuda_runtime.h>
#include <cuda_fp16.h>
#include <cstdint>
#include <cstddef>

// ============================================================================
// helpers (base sm_103 ISA only: ldmatrix + mma.sync + cp.async)
// ============================================================================
__device__ __forceinline__ uint32_t smem_u32(const void* p) {
    uint32_t a;
    asm("{ .reg .u64 t; cvta.to.shared.u64 t, %1; cvt.u32.u64 %0, t; }"
        : "=r"(a) : "l"(p));
    return a;
}

#define CP16(dst, src) \
    asm volatile("cp.async.cg.shared.global [%0], [%1], 16;" \
                 :: "r"(dst), "l"(src) : "memory")
#define CP_COMMIT() asm volatile("cp.async.commit_group;" ::: "memory")
#define CP_WAIT1()  asm volatile("cp.async.wait_group 1;" ::: "memory")
#define CP_WAIT0()  asm volatile("cp.async.wait_group 0;" ::: "memory")

#define LDSM4(r, addr) \
    asm volatile("ldmatrix.sync.aligned.m8n8.x4.shared.b16 {%0,%1,%2,%3}, [%4];" \
                 : "=r"((r)[0]), "=r"((r)[1]), "=r"((r)[2]), "=r"((r)[3]) : "r"(addr))

#define MMA16816(d, a, b0, b1) \
    asm volatile("mma.sync.aligned.m16n8k16.row.col.f32.f16.f16.f32 " \
                 "{%0,%1,%2,%3},{%4,%5,%6,%7},{%8,%9},{%0,%1,%2,%3};" \
                 : "+f"((d)[0]), "+f"((d)[1]), "+f"((d)[2]), "+f"((d)[3]) \
                 : "r"((a)[0]), "r"((a)[1]), "r"((a)[2]), "r"((a)[3]), \
                   "r"(b0), "r"(b1))

#define STS128U(addr, r) \
    asm volatile("st.shared.v4.b32 [%0], {%1, %2, %3, %4};" \
                 :: "r"(addr), "r"((r)[0]), "r"((r)[1]), "r"((r)[2]), "r"((r)[3]) : "memory")

__device__ __forceinline__ uint32_t packh2(float f0, float f1) {
    __half2 t = __halves2half2(__float2half_rn(f0), __float2half_rn(f1));
    return *reinterpret_cast<uint32_t*>(&t);
}

// ============================================================================
// Scratch (device globals; no allocations allowed)
// ============================================================================
__device__ __align__(16) __half g_w_h[6 * 1048576];      // [M1,M2,Wq,Wk,Wv,Wo] fp16
__device__ __align__(16) __half g_enh_hi[4194304], g_enh_lo[4194304];  // [mem;x]
__device__ __align__(16) __half g_h_hi[2097152],  g_h_lo[2097152];
__device__ __align__(16) __half g_q_h[4194304];          // Q single fp16 (QK single-pass)
__device__ __align__(16) __half g_k_h[4194304];          // K single fp16
__device__ __align__(16) __half g_vt_h[4194304];         // V^T [32][64][2048], single
__device__ __align__(16) __half g_ctx_hi[2097152], g_ctx_lo[2097152];
__device__ __align__(16) float g_sc[16777216];   // 67 MB: raw scores, 4 heads (L2-hot)

// ============================================================================
// fp32 -> fp16 conversions
// ============================================================================
__global__ void __launch_bounds__(256) conv_w_kernel(
    const float* __restrict__ s0, const float* __restrict__ s1,
    const float* __restrict__ s2, const float* __restrict__ s3,
    const float* __restrict__ s4, const float* __restrict__ s5,
    __half* __restrict__ hi)
{
    const int w = blockIdx.y;
    const float* src = (w == 0) ? s0 : (w == 1) ? s1 : (w == 2) ? s2
                    : (w == 3) ? s3 : (w == 4) ? s4 : s5;
    hi += (size_t)w * 1048576;
    int i = blockIdx.x * 256 + threadIdx.x;           // n4 = 262144
    float4 v = reinterpret_cast<const float4*>(src)[i];
    reinterpret_cast<__half2*>(hi)[2 * i]     = __halves2half2(__float2half_rn(v.x), __float2half_rn(v.y));
    reinterpret_cast<__half2*>(hi)[2 * i + 1] = __halves2half2(__float2half_rn(v.z), __float2half_rn(v.w));
}

__global__ void __launch_bounds__(256) conv_kernel(
    const float* __restrict__ src, __half* __restrict__ hi,
    __half* __restrict__ lo, int n4)
{
    int i = blockIdx.x * 256 + threadIdx.x;
    if (i >= n4) return;
    float4 v = reinterpret_cast<const float4*>(src)[i];
    float vals[4] = {v.x, v.y, v.z, v.w};
    __half h[4], l[4];
#pragma unroll
    for (int j = 0; j < 4; ++j) {
        h[j] = __float2half_rn(vals[j]);
        l[j] = __float2half_rn(vals[j] - __half2float(h[j]));
    }
    reinterpret_cast<__half2*>(hi)[2 * i]     = __halves2half2(h[0], h[1]);
    reinterpret_cast<__half2*>(hi)[2 * i + 1] = __halves2half2(h[2], h[3]);
    reinterpret_cast<__half2*>(lo)[2 * i]     = __halves2half2(l[0], l[1]);
    reinterpret_cast<__half2*>(lo)[2 * i + 1] = __halves2half2(l[2], l[3]);
}

// ============================================================================
// fp16 NT GEMM via mma.sync: C = act(scale*(A@B^T) + bias)
// PASSES=2: A split hi/lo fp16 (Ahi*B + Alo*B).  PASSES=1: Ahi*B only.
// B always single fp16. CTA tile 128 x BN, 8 warps, BK=32, 2-stage cp.async.
// MODE 0: plain    MODE 1: QK (z=zbase+bz; C=scratch local z)
// MODE 2: AV       A from fp32 attn lower half (__ldcs) + in-kernel fp16 round
// transV: scatter C into Vt[32][64][2048]
// ============================================================================
template <int BN, int MODE, int PASSES>
__global__ void __launch_bounds__(256, 2) gemm2_mma(
    const __half* __restrict__ Ahi, const __half* __restrict__ Alo,
    const float* __restrict__ Af,
    const __half* __restrict__ Bh,
    const float* __restrict__ bias,
    float* __restrict__ Cf, __half* __restrict__ Chi, __half* __restrict__ Clo,
    int K, int lda, int ldb, int ldc,
    float scale, int relu, int zbase, int transV)
{
    extern __shared__ __align__(128) char smem[];
    constexpr int STRIDE = 80;                  // 64B row + 16B pad
    constexpr int A_BYTES = 128 * STRIDE;       // 10240
    constexpr int B_BYTES = BN * STRIDE;
    constexpr int STAGE = PASSES * A_BYTES + B_BYTES;
    constexpr int WM = (BN == 128) ? 2 : 1;

    const int tid = threadIdx.x;
    const int wid = tid >> 5, lid = tid & 31;
    const int m0 = blockIdx.y * 128;
    const int n0 = blockIdx.x * BN;
    const int z  = (MODE == 1) ? (zbase + blockIdx.z) : blockIdx.z;

    const int r0 = (BN == 128) ? ((wid >> 1) * 32) : (wid * 16);
    const int c0 = (BN == 128) ? ((wid & 1) * 64) : 0;

    size_t aOff = 0, bOff = 0;
    if (MODE == 1) {
        aOff = bOff = (size_t)(z >> 4) * 2097152 + (size_t)(z & 15) * 64;
    } else if (MODE == 2) {
        bOff = (size_t)z * 131072;
    }
    if (MODE != 2) { Ahi += aOff; if (PASSES == 2) Alo += aOff; }
    Bh += bOff;

    const uint32_t sbase = smem_u32(smem);

    auto issueA = [&](int c) {
        const int kt = c << 5;
        const uint32_t sb = sbase + (c & 1) * STAGE;
#pragma unroll
        for (int u = 0; u < 2; ++u) {
            int id = tid + u * 256;
            int row = id >> 2, seg = id & 3;
            const char* sH = (const char*)(Ahi + (size_t)(m0 + row) * lda + kt) + seg * 16;
            uint32_t d = sb + row * STRIDE + seg * 16;
            CP16(d, sH);
            if (PASSES == 2) {
                const char* sL = (const char*)(Alo + (size_t)(m0 + row) * lda + kt) + seg * 16;
                CP16(d + A_BYTES, sL);
            }
        }
    };
    auto issueB = [&](int c) {
        const int kt = c << 5;
        const uint32_t sb = sbase + (c & 1) * STAGE;
        constexpr int BU = (BN * 4) / 256;
#pragma unroll
        for (int u = 0; u < BU; ++u) {
            int id = tid + u * 256;
            int row = id >> 2, seg = id & 3;
            const char* sH = (const char*)(Bh + (size_t)(n0 + row) * ldb + kt) + seg * 16;
            uint32_t d = sb + PASSES * A_BYTES + row * STRIDE + seg * 16;
            CP16(d, sH);
        }
    };

    float acc[WM][8][4];
#pragma unroll
    for (int i = 0; i < WM; ++i)
#pragma unroll
        for (int j = 0; j < 8; ++j)
#pragma unroll
            for (int q = 0; q < 4; ++q) acc[i][j][q] = 0.0f;

    const uint32_t aRow = (uint32_t)(r0 + (lid & 15)) * STRIDE + ((lid >> 4) & 1) * 16;
    const uint32_t bRow = (uint32_t)(c0 + (lid & 7) + ((lid >> 4) & 1) * 8) * STRIDE
                        + ((lid >> 3) & 1) * 16;

    auto mma_chunk = [&](int c) {
        const uint32_t sb = sbase + (c & 1) * STAGE;
        const uint32_t aH = sb, aL = sb + A_BYTES;
        const uint32_t bB = sb + PASSES * A_BYTES;
#pragma unroll
        for (int s = 0; s < 2; ++s) {
            uint32_t ah[WM][4], al[WM][4], bb[4][4];
#pragma unroll
            for (int i = 0; i < WM; ++i) {
                LDSM4(ah[i], aH + aRow + i * 16 * STRIDE + s * 32);
                if (PASSES == 2) LDSM4(al[i], aL + aRow + i * 16 * STRIDE + s * 32);
            }
#pragma unroll
            for (int j = 0; j < 4; ++j)
                LDSM4(bb[j], bB + bRow + j * 16 * STRIDE + s * 32);
#pragma unroll
            for (int i = 0; i < WM; ++i)
#pragma unroll
                for (int jt = 0; jt < 8; ++jt) {
                    MMA16816(acc[i][jt], ah[i], bb[jt >> 1][(jt & 1) * 2], bb[jt >> 1][(jt & 1) * 2 + 1]);
                    if (PASSES == 2)
                        MMA16816(acc[i][jt], al[i], bb[jt >> 1][(jt & 1) * 2], bb[jt >> 1][(jt & 1) * 2 + 1]);
                }
        }
    };

    const int nC = K >> 5;

    if constexpr (MODE != 2) {
        issueA(0); issueB(0); CP_COMMIT();
        for (int c = 0; c < nC; ++c) {
            if (c + 1 < nC) { issueA(c + 1); issueB(c + 1); CP_COMMIT(); CP_WAIT1(); }
            else            { CP_WAIT0(); }
            __syncthreads();
            mma_chunk(c);
            __syncthreads();
        }
    } else {
        // A from fp32 attn (lower half): reg-staged __ldcs + fp16 round + STS
        const float* Abase = Af + (size_t)z * 4194304 + (size_t)1024 * 2048;
        const int arow = tid >> 1, acol = (tid & 1) * 16;
        const float* Aptr = Abase + (size_t)(m0 + arow) * 2048 + acol;

        auto ldA = [&](int c, float4* r) {
            const float4* p = reinterpret_cast<const float4*>(Aptr + (c << 5));
#pragma unroll
            for (int j = 0; j < 4; ++j) r[j] = __ldcs(p + j);
        };
        auto stsA = [&](int c, const float4* r) {
            const uint32_t sb = sbase + (c & 1) * STAGE;
            const uint32_t d = sb + arow * STRIDE + acol * 2;
#pragma unroll
            for (int half = 0; half < 2; ++half) {
                float f[8] = {r[2 * half].x, r[2 * half].y, r[2 * half].z, r[2 * half].w,
                              r[2 * half + 1].x, r[2 * half + 1].y,
                              r[2 * half + 1].z, r[2 * half + 1].w};
                uint32_t hp[4], lp[4];
#pragma unroll
                for (int q = 0; q < 4; ++q) {
                    float f0 = f[2 * q], f1 = f[2 * q + 1];
                    hp[q] = packh2(f0, f1);
                    if (PASSES == 2) {
                        __half h0 = __float2half_rn(f0), h1 = __float2half_rn(f1);
                        lp[q] = packh2(f0 - __half2float(h0), f1 - __half2float(h1));
                    }
                }
                STS128U(d + half * 16, hp);
                if (PASSES == 2) STS128U(d + half * 16 + A_BYTES, lp);
            }
        };

        float4 cur[4], nxt[4];
        ldA(0, cur);
        issueB(0); CP_COMMIT();
        for (int c = 0; c < nC; ++c) {
            stsA(c, cur);
            if (c + 1 < nC) { ldA(c + 1, nxt); issueB(c + 1); CP_COMMIT(); CP_WAIT1(); }
            else            { CP_WAIT0(); }
            __syncthreads();
            mma_chunk(c);
            __syncthreads();
#pragma unroll
            for (int j = 0; j < 4; ++j) cur[j] = nxt[j];
        }
    }

    // ---------------- epilogue ----------------
    size_t cOffZ = 0;
    if constexpr (MODE == 1)      cOffZ = (size_t)blockIdx.z * 4194304;     // local z in scratch
    else if constexpr (MODE == 2) cOffZ = (size_t)(z >> 4) * 1048576 + (size_t)(z & 15) * 64;

    const int grp = lid >> 2, tig = lid & 3;

#pragma unroll
    for (int i = 0; i < WM; ++i) {
#pragma unroll
        for (int jt = 0; jt < 8; ++jt) {
            const int mr = m0 + r0 + i * 16 + grp;
            const int nc = n0 + c0 + jt * 8 + tig * 2;
            float v0 = acc[i][jt][0] * scale, v1 = acc[i][jt][1] * scale;
            float v2 = acc[i][jt][2] * scale, v3 = acc[i][jt][3] * scale;
            if (bias) {
                float b0 = __ldg(bias + nc), b1 = __ldg(bias + nc + 1);
                v0 += b0; v1 += b1; v2 += b0; v3 += b1;
            }
            if (relu) {
                v0 = fmaxf(v0, 0.0f); v1 = fmaxf(v1, 0.0f);
                v2 = fmaxf(v2, 0.0f); v3 = fmaxf(v3, 0.0f);
            }
            if (Cf) {
                *reinterpret_cast<float2*>(&Cf[cOffZ + (size_t)mr * ldc + nc]) =
                    make_float2(v0, v1);
                *reinterpret_cast<float2*>(&Cf[cOffZ + (size_t)(mr + 8) * ldc + nc]) =
                    make_float2(v2, v3);
            }
            if (Chi) {
                __half h0 = __float2half_rn(v0), h1 = __float2half_rn(v1);
                __half h2 = __float2half_rn(v2), h3 = __float2half_rn(v3);
                if (!transV) {
                    size_t i0 = cOffZ + (size_t)mr * ldc + nc;
                    size_t i1 = cOffZ + (size_t)(mr + 8) * ldc + nc;
                    *reinterpret_cast<__half2*>(&Chi[i0]) = __halves2half2(h0, h1);
                    *reinterpret_cast<__half2*>(&Chi[i1]) = __halves2half2(h2, h3);
                    if (Clo) {
                        __half l0 = __float2half_rn(v0 - __half2float(h0));
                        __half l1 = __float2half_rn(v1 - __half2float(h1));
                        __half l2 = __float2half_rn(v2 - __half2float(h2));
                        __half l3 = __float2half_rn(v3 - __half2float(h3));
                        *reinterpret_cast<__half2*>(&Clo[i0]) = __halves2half2(l0, l1);
                        *reinterpret_cast<__half2*>(&Clo[i1]) = __halves2half2(l2, l3);
                    }
                } else {
#pragma unroll
                    for (int e = 0; e < 4; ++e) {
                        int rr = mr + (e >> 1) * 8;
                        int nn = nc + (e & 1);
                        size_t idx = ((size_t)(rr >> 11) * 16 + (size_t)(nn >> 6)) * 131072
                                   + (size_t)(nn & 63) * 2048 + (size_t)(rr & 2047);
                        __half hv = (e == 0) ? h0 : (e == 1) ? h1 : (e == 2) ? h2 : h3;
                        Chi[idx] = hv;
                    }
                }
            }
        }
    }
}

// ============================================================================
// Row softmax: scratch (L2-hot, 4 heads) -> attn output (streaming .cs)
// ============================================================================
__global__ void __launch_bounds__(256) softmax_kernel(
    const float* __restrict__ scratch, float* __restrict__ attn, int zbase)
{
    const int zloc = blockIdx.x >> 11;
    const int rr = blockIdx.x & 2047;
    const float4* p = reinterpret_cast<const float4*>(
        scratch + (size_t)zloc * 4194304 + (size_t)rr * 2048);
    float4* q = reinterpret_cast<float4*>(
        attn + (size_t)(zbase + zloc) * 4194304 + (size_t)rr * 2048);
    const int tid = threadIdx.x;
    float4 v0 = p[tid];
    float4 v1 = p[tid + 256];

    float mx = fmaxf(fmaxf(fmaxf(v0.x, v0.y), fmaxf(v0.z, v0.w)),
                     fmaxf(fmaxf(v1.x, v1.y), fmaxf(v1.z, v1.w)));
#pragma unroll
    for (int o = 16; o; o >>= 1) mx = fmaxf(mx, __shfl_xor_sync(0xffffffffu, mx, o));

    __shared__ float smax[8], ssum[8];
    if ((tid & 31) == 0) smax[tid >> 5] = mx;
    __syncthreads();
    float m = smax[0];
#pragma unroll
    for (int i = 1; i < 8; i++) m = fmaxf(m, smax[i]);

    v0.x = __expf(v0.x - m); v0.y = __expf(v0.y - m);
    v0.z = __expf(v0.z - m); v0.w = __expf(v0.w - m);
    v1.x = __expf(v1.x - m); v1.y = __expf(v1.y - m);
    v1.z = __expf(v1.z - m); v1.w = __expf(v1.w - m);

    float s = v0.x + v0.y + v0.z + v0.w + v1.x + v1.y + v1.z + v1.w;
#pragma unroll
    for (int o = 16; o; o >>= 1) s += __shfl_xor_sync(0xffffffffu, s, o);
    if ((tid & 31) == 0) ssum[tid >> 5] = s;
    __syncthreads();
    float tot = 0.0f;
#pragma unroll
    for (int i = 0; i < 8; i++) tot += ssum[i];
    const float inv = 1.0f / tot;

    v0.x *= inv; v0.y *= inv; v0.z *= inv; v0.w *= inv;
    v1.x *= inv; v1.y *= inv; v1.z *= inv; v1.w *= inv;
    __stcs(q + tid, v0);
    __stcs(q + tid + 256, v1);
}

// ============================================================================
// Launch
// ============================================================================
extern "C" void kernel_launch(void* const* d_in, const int* in_sizes, int n_in,
                              void* d_out, int out_size)
{
    const float* x   = (const float*)d_in[0];
    const float* Wq  = (const float*)d_in[1];
    const float* bq  = (const float*)d_in[2];
    const float* Wk  = (const float*)d_in[3];
    const float* bk  = (const float*)d_in[4];
    const float* Wv  = (const float*)d_in[5];
    const float* bv  = (const float*)d_in[6];
    const float* Wo  = (const float*)d_in[7];
    const float* bo  = (const float*)d_in[8];
    const float* M1  = (const float*)d_in[9];
    const float* bm1 = (const float*)d_in[10];
    const float* M2  = (const float*)d_in[11];
    const float* bm2 = (const float*)d_in[12];

    float* out  = (float*)d_out;                      // (2,1024,1024)
    float* attn = out + (size_t)2 * 1024 * 1024;      // (2,16,2048,2048)

    __half *wH, *enhHi, *enhLo, *hHi, *hLo, *qH, *kH, *vtH, *cxHi, *cxLo;
    float* sc;
    cudaGetSymbolAddress((void**)&wH,   g_w_h);
    cudaGetSymbolAddress((void**)&enhHi, g_enh_hi);
    cudaGetSymbolAddress((void**)&enhLo, g_enh_lo);
    cudaGetSymbolAddress((void**)&hHi,  g_h_hi);
    cudaGetSymbolAddress((void**)&hLo,  g_h_lo);
    cudaGetSymbolAddress((void**)&qH,   g_q_h);
    cudaGetSymbolAddress((void**)&kH,   g_k_h);
    cudaGetSymbolAddress((void**)&vtH,  g_vt_h);
    cudaGetSymbolAddress((void**)&cxHi, g_ctx_hi);
    cudaGetSymbolAddress((void**)&cxLo, g_ctx_lo);
    cudaGetSymbolAddress((void**)&sc,   g_sc);

    const size_t MW = 1048576;
    const int SMEM128_P2 = 2 * (2 * 10240 + 128 * 80);   // 61440
    const int SMEM128_P1 = 2 * (1 * 10240 + 128 * 80);   // 40960
    const int SMEM64_P1  = 2 * (1 * 10240 + 64 * 80);    // 30720
    cudaFuncSetAttribute(gemm2_mma<128, 0, 2>, cudaFuncAttributeMaxDynamicSharedMemorySize, SMEM128_P2);
    cudaFuncSetAttribute(gemm2_mma<128, 0, 1>, cudaFuncAttributeMaxDynamicSharedMemorySize, SMEM128_P1);
    cudaFuncSetAttribute(gemm2_mma<128, 1, 1>, cudaFuncAttributeMaxDynamicSharedMemorySize, SMEM128_P1);
    cudaFuncSetAttribute(gemm2_mma<64, 2, 1>,  cudaFuncAttributeMaxDynamicSharedMemorySize, SMEM64_P1);

    // 0) convert weights (single fp16) + x (hi/lo fp16)
    conv_w_kernel<<<dim3(1024, 6), 256>>>(M1, M2, Wq, Wk, Wv, Wo, wH);
    conv_kernel<<<2048, 256>>>(x, enhHi + 2097152, enhLo + 2097152, 524288);

    // 1) h = relu(x @ M1^T + bm1)   (2-pass)
    gemm2_mma<128, 0, 2><<<dim3(8, 16), 256, SMEM128_P2>>>(
        enhHi + 2097152, enhLo + 2097152, nullptr, wH + 0 * MW, bm1,
        nullptr, hHi, hLo, 1024, 1024, 1024, 1024, 1.0f, 1, 0, 0);
    // 2) enh[0:2048] = h @ M2^T + bm2   (2-pass)
    gemm2_mma<128, 0, 2><<<dim3(8, 16), 256, SMEM128_P2>>>(
        hHi, hLo, nullptr, wH + 1 * MW, bm2,
        nullptr, enhHi, enhLo, 1024, 1024, 1024, 1024, 1.0f, 0, 0, 0);
    // 3) Q (2-pass, single store), K/V (1-pass, single store; V transposed)
    gemm2_mma<128, 0, 2><<<dim3(8, 32), 256, SMEM128_P2>>>(
        enhHi, enhLo, nullptr, wH + 2 * MW, bq,
        nullptr, qH, nullptr, 1024, 1024, 1024, 1024, 1.0f, 0, 0, 0);
    gemm2_mma<128, 0, 1><<<dim3(8, 32), 256, SMEM128_P1>>>(
        enhHi, nullptr, nullptr, wH + 3 * MW, bk,
        nullptr, kH, nullptr, 1024, 1024, 1024, 1024, 1.0f, 0, 0, 0);
    gemm2_mma<128, 0, 1><<<dim3(8, 32), 256, SMEM128_P1>>>(
        enhHi, nullptr, nullptr, wH + 4 * MW, bv,
        nullptr, vtH, nullptr, 1024, 1024, 1024, 1024, 1.0f, 0, 0, 1);

    // 4+5) per 4-head group: QK scores (1-pass) -> L2-hot scratch, softmax -> attn
    for (int g = 0; g < 8; ++g) {
        gemm2_mma<128, 1, 1><<<dim3(16, 16, 4), 256, SMEM128_P1>>>(
            qH, nullptr, nullptr, kH, nullptr,
            sc, nullptr, nullptr, 64, 1024, 1024, 2048, 0.125f, 0, g * 4, 0);
        softmax_kernel<<<8192, 256>>>(sc, attn, g * 4);
    }

    // 6) ctx = attn[., 1024:, :] @ V_bh  (1-pass, A = fp32 attn rounded in-kernel)
    gemm2_mma<64, 2, 1><<<dim3(1, 8, 32), 256, SMEM64_P1>>>(
        nullptr, nullptr, attn, vtH, nullptr,
        nullptr, cxHi, cxLo, 2048, 2048, 2048, 1024, 1.0f, 0, 0, 0);
    // 7) out = ctx @ Wo^T + bo  (2-pass, fp32 out)
    gemm2_mma<128, 0, 2><<<dim3(8, 16), 256, SMEM128_P2>>>(
        cxHi, cxLo, nullptr, wH + 5 * MW, bo,
        out, nullptr, nullptr, 1024, 1024, 1024, 1024, 1.0f, 0, 0, 0);
}

// round 14
// speedup vs baseline: 1.6770x; 1.0489x over previous
#include <cuda_runtime.h>
#include <cuda_fp16.h>
#include <cstdint>
#include <cstddef>

// ============================================================================
// helpers (base sm_103 ISA only: ldmatrix + mma.sync + cp.async)
// ============================================================================
__device__ __forceinline__ uint32_t smem_u32(const void* p) {
    uint32_t a;
    asm("{ .reg .u64 t; cvta.to.shared.u64 t, %1; cvt.u32.u64 %0, t; }"
        : "=r"(a) : "l"(p));
    return a;
}

#define CP16(dst, src) \
    asm volatile("cp.async.cg.shared.global [%0], [%1], 16;" \
                 :: "r"(dst), "l"(src) : "memory")
#define CP_COMMIT() asm volatile("cp.async.commit_group;" ::: "memory")
#define CP_WAIT1()  asm volatile("cp.async.wait_group 1;" ::: "memory")
#define CP_WAIT0()  asm volatile("cp.async.wait_group 0;" ::: "memory")

#define LDSM4(r, addr) \
    asm volatile("ldmatrix.sync.aligned.m8n8.x4.shared.b16 {%0,%1,%2,%3}, [%4];" \
                 : "=r"((r)[0]), "=r"((r)[1]), "=r"((r)[2]), "=r"((r)[3]) : "r"(addr))

#define MMA16816(d, a, b0, b1) \
    asm volatile("mma.sync.aligned.m16n8k16.row.col.f32.f16.f16.f32 " \
                 "{%0,%1,%2,%3},{%4,%5,%6,%7},{%8,%9},{%0,%1,%2,%3};" \
                 : "+f"((d)[0]), "+f"((d)[1]), "+f"((d)[2]), "+f"((d)[3]) \
                 : "r"((a)[0]), "r"((a)[1]), "r"((a)[2]), "r"((a)[3]), \
                   "r"(b0), "r"(b1))

#define STS128U(addr, r) \
    asm volatile("st.shared.v4.b32 [%0], {%1, %2, %3, %4};" \
                 :: "r"(addr), "r"((r)[0]), "r"((r)[1]), "r"((r)[2]), "r"((r)[3]) : "memory")

__device__ __forceinline__ uint32_t packh2(float f0, float f1) {
    __half2 t = __halves2half2(__float2half_rn(f0), __float2half_rn(f1));
    return *reinterpret_cast<uint32_t*>(&t);
}

// ============================================================================
// Scratch (device globals; no allocations allowed)
// ============================================================================
__device__ __align__(16) __half g_w_h[6 * 1048576];      // [M1,M2,Wq,Wk,Wv,Wo] fp16
__device__ __align__(16) __half g_enh_hi[4194304], g_enh_lo[4194304];  // [mem;x]
__device__ __align__(16) __half g_h_hi[2097152],  g_h_lo[2097152];
__device__ __align__(16) __half g_q_h[4194304];          // Q single fp16
__device__ __align__(16) __half g_k_h[4194304];          // K single fp16
__device__ __align__(16) __half g_vt_h[4194304];         // V^T [32][64][2048], single
__device__ __align__(16) __half g_ctx_hi[2097152], g_ctx_lo[2097152];
__device__ __align__(16) __half g_sc[2 * 16777216];      // 67 MB: fp16 logits, 2 bufs x 4 heads (L2-hot)

// ============================================================================
// fp32 -> fp16 conversions
// ============================================================================
__global__ void __launch_bounds__(256) conv_w_kernel(
    const float* __restrict__ s0, const float* __restrict__ s1,
    const float* __restrict__ s2, const float* __restrict__ s3,
    const float* __restrict__ s4, const float* __restrict__ s5,
    __half* __restrict__ hi)
{
    const int w = blockIdx.y;
    const float* src = (w == 0) ? s0 : (w == 1) ? s1 : (w == 2) ? s2
                    : (w == 3) ? s3 : (w == 4) ? s4 : s5;
    hi += (size_t)w * 1048576;
    int i = blockIdx.x * 256 + threadIdx.x;           // n4 = 262144
    float4 v = reinterpret_cast<const float4*>(src)[i];
    reinterpret_cast<__half2*>(hi)[2 * i]     = __halves2half2(__float2half_rn(v.x), __float2half_rn(v.y));
    reinterpret_cast<__half2*>(hi)[2 * i + 1] = __halves2half2(__float2half_rn(v.z), __float2half_rn(v.w));
}

__global__ void __launch_bounds__(256) conv_kernel(
    const float* __restrict__ src, __half* __restrict__ hi,
    __half* __restrict__ lo, int n4)
{
    int i = blockIdx.x * 256 + threadIdx.x;
    if (i >= n4) return;
    float4 v = reinterpret_cast<const float4*>(src)[i];
    float vals[4] = {v.x, v.y, v.z, v.w};
    __half h[4], l[4];
#pragma unroll
    for (int j = 0; j < 4; ++j) {
        h[j] = __float2half_rn(vals[j]);
        l[j] = __float2half_rn(vals[j] - __half2float(h[j]));
    }
    reinterpret_cast<__half2*>(hi)[2 * i]     = __halves2half2(h[0], h[1]);
    reinterpret_cast<__half2*>(hi)[2 * i + 1] = __halves2half2(h[2], h[3]);
    reinterpret_cast<__half2*>(lo)[2 * i]     = __halves2half2(l[0], l[1]);
    reinterpret_cast<__half2*>(lo)[2 * i + 1] = __halves2half2(l[2], l[3]);
}

// ============================================================================
// fp16 NT GEMM via mma.sync: C = act(scale*(A@B^T) + bias)
// PASSES=2: A split hi/lo fp16.  PASSES=1: Ahi*B only.  B single fp16.
// CTA tile 128 x BN, 8 warps, BK=32, 2-stage cp.async.
// MODE 0: plain    MODE 1: QK (z=zbase+bz; fp16 logits -> scratch local z)
// MODE 2: AV       A from fp32 attn lower half (__ldcs) + in-kernel fp16 round
// transV: scatter C into Vt[32][64][2048]
// ============================================================================
template <int BN, int MODE, int PASSES>
__global__ void __launch_bounds__(256, 2) gemm2_mma(
    const __half* __restrict__ Ahi, const __half* __restrict__ Alo,
    const float* __restrict__ Af,
    const __half* __restrict__ Bh,
    const float* __restrict__ bias,
    float* __restrict__ Cf, __half* __restrict__ Chi, __half* __restrict__ Clo,
    int K, int lda, int ldb, int ldc,
    float scale, int relu, int zbase, int transV)
{
    extern __shared__ __align__(128) char smem[];
    constexpr int STRIDE = 80;                  // 64B row + 16B pad
    constexpr int A_BYTES = 128 * STRIDE;       // 10240
    constexpr int B_BYTES = BN * STRIDE;
    constexpr int STAGE = PASSES * A_BYTES + B_BYTES;
    constexpr int WM = (BN == 128) ? 2 : 1;

    const int tid = threadIdx.x;
    const int wid = tid >> 5, lid = tid & 31;
    const int m0 = blockIdx.y * 128;
    const int n0 = blockIdx.x * BN;
    const int z  = (MODE == 1) ? (zbase + blockIdx.z) : blockIdx.z;

    const int r0 = (BN == 128) ? ((wid >> 1) * 32) : (wid * 16);
    const int c0 = (BN == 128) ? ((wid & 1) * 64) : 0;

    size_t aOff = 0, bOff = 0;
    if (MODE == 1) {
        aOff = bOff = (size_t)(z >> 4) * 2097152 + (size_t)(z & 15) * 64;
    } else if (MODE == 2) {
        bOff = (size_t)z * 131072;
    }
    if (MODE != 2) { Ahi += aOff; if (PASSES == 2) Alo += aOff; }
    Bh += bOff;

    const uint32_t sbase = smem_u32(smem);

    auto issueA = [&](int c) {
        const int kt = c << 5;
        const uint32_t sb = sbase + (c & 1) * STAGE;
#pragma unroll
        for (int u = 0; u < 2; ++u) {
            int id = tid + u * 256;
            int row = id >> 2, seg = id & 3;
            const char* sH = (const char*)(Ahi + (size_t)(m0 + row) * lda + kt) + seg * 16;
            uint32_t d = sb + row * STRIDE + seg * 16;
            CP16(d, sH);
            if (PASSES == 2) {
                const char* sL = (const char*)(Alo + (size_t)(m0 + row) * lda + kt) + seg * 16;
                CP16(d + A_BYTES, sL);
            }
        }
    };
    auto issueB = [&](int c) {
        const int kt = c << 5;
        const uint32_t sb = sbase + (c & 1) * STAGE;
        constexpr int BU = (BN * 4) / 256;
#pragma unroll
        for (int u = 0; u < BU; ++u) {
            int id = tid + u * 256;
            int row = id >> 2, seg = id & 3;
            const char* sH = (const char*)(Bh + (size_t)(n0 + row) * ldb + kt) + seg * 16;
            uint32_t d = sb + PASSES * A_BYTES + row * STRIDE + seg * 16;
            CP16(d, sH);
        }
    };

    float acc[WM][8][4];
#pragma unroll
    for (int i = 0; i < WM; ++i)
#pragma unroll
        for (int j = 0; j < 8; ++j)
#pragma unroll
            for (int q = 0; q < 4; ++q) acc[i][j][q] = 0.0f;

    const uint32_t aRow = (uint32_t)(r0 + (lid & 15)) * STRIDE + ((lid >> 4) & 1) * 16;
    const uint32_t bRow = (uint32_t)(c0 + (lid & 7) + ((lid >> 4) & 1) * 8) * STRIDE
                        + ((lid >> 3) & 1) * 16;

    auto mma_chunk = [&](int c) {
        const uint32_t sb = sbase + (c & 1) * STAGE;
        const uint32_t aH = sb, aL = sb + A_BYTES;
        const uint32_t bB = sb + PASSES * A_BYTES;
#pragma unroll
        for (int s = 0; s < 2; ++s) {
            uint32_t ah[WM][4], al[WM][4], bb[4][4];
#pragma unroll
            for (int i = 0; i < WM; ++i) {
                LDSM4(ah[i], aH + aRow + i * 16 * STRIDE + s * 32);
                if (PASSES == 2) LDSM4(al[i], aL + aRow + i * 16 * STRIDE + s * 32);
            }
#pragma unroll
            for (int j = 0; j < 4; ++j)
                LDSM4(bb[j], bB + bRow + j * 16 * STRIDE + s * 32);
#pragma unroll
            for (int i = 0; i < WM; ++i)
#pragma unroll
                for (int jt = 0; jt < 8; ++jt) {
                    MMA16816(acc[i][jt], ah[i], bb[jt >> 1][(jt & 1) * 2], bb[jt >> 1][(jt & 1) * 2 + 1]);
                    if (PASSES == 2)
                        MMA16816(acc[i][jt], al[i], bb[jt >> 1][(jt & 1) * 2], bb[jt >> 1][(jt & 1) * 2 + 1]);
                }
        }
    };

    const int nC = K >> 5;

    if constexpr (MODE != 2) {
        issueA(0); issueB(0); CP_COMMIT();
        for (int c = 0; c < nC; ++c) {
            if (c + 1 < nC) { issueA(c + 1); issueB(c + 1); CP_COMMIT(); CP_WAIT1(); }
            else            { CP_WAIT0(); }
            __syncthreads();
            mma_chunk(c);
            __syncthreads();
        }
    } else {
        // A from fp32 attn (lower half): reg-staged __ldcs + fp16 round + STS
        const float* Abase = Af + (size_t)z * 4194304 + (size_t)1024 * 2048;
        const int arow = tid >> 1, acol = (tid & 1) * 16;
        const float* Aptr = Abase + (size_t)(m0 + arow) * 2048 + acol;

        auto ldA = [&](int c, float4* r) {
            const float4* p = reinterpret_cast<const float4*>(Aptr + (c << 5));
#pragma unroll
            for (int j = 0; j < 4; ++j) r[j] = __ldcs(p + j);
        };
        auto stsA = [&](int c, const float4* r) {
            const uint32_t sb = sbase + (c & 1) * STAGE;
            const uint32_t d = sb + arow * STRIDE + acol * 2;
#pragma unroll
            for (int half = 0; half < 2; ++half) {
                float f[8] = {r[2 * half].x, r[2 * half].y, r[2 * half].z, r[2 * half].w,
                              r[2 * half + 1].x, r[2 * half + 1].y,
                              r[2 * half + 1].z, r[2 * half + 1].w};
                uint32_t hp[4];
#pragma unroll
                for (int q = 0; q < 4; ++q)
                    hp[q] = packh2(f[2 * q], f[2 * q + 1]);
                STS128U(d + half * 16, hp);
            }
        };

        float4 cur[4], nxt[4];
        ldA(0, cur);
        issueB(0); CP_COMMIT();
        for (int c = 0; c < nC; ++c) {
            stsA(c, cur);
            if (c + 1 < nC) { ldA(c + 1, nxt); issueB(c + 1); CP_COMMIT(); CP_WAIT1(); }
            else            { CP_WAIT0(); }
            __syncthreads();
            mma_chunk(c);
            __syncthreads();
#pragma unroll
            for (int j = 0; j < 4; ++j) cur[j] = nxt[j];
        }
    }

    // ---------------- epilogue ----------------
    size_t cOffZ = 0;
    if constexpr (MODE == 1)      cOffZ = (size_t)blockIdx.z * 4194304;     // local z in scratch (halves)
    else if constexpr (MODE == 2) cOffZ = (size_t)(z >> 4) * 1048576 + (size_t)(z & 15) * 64;

    const int grp = lid >> 2, tig = lid & 3;

#pragma unroll
    for (int i = 0; i < WM; ++i) {
#pragma unroll
        for (int jt = 0; jt < 8; ++jt) {
            const int mr = m0 + r0 + i * 16 + grp;
            const int nc = n0 + c0 + jt * 8 + tig * 2;
            float v0 = acc[i][jt][0] * scale, v1 = acc[i][jt][1] * scale;
            float v2 = acc[i][jt][2] * scale, v3 = acc[i][jt][3] * scale;
            if (bias) {
                float b0 = __ldg(bias + nc), b1 = __ldg(bias + nc + 1);
                v0 += b0; v1 += b1; v2 += b0; v3 += b1;
            }
            if (relu) {
                v0 = fmaxf(v0, 0.0f); v1 = fmaxf(v1, 0.0f);
                v2 = fmaxf(v2, 0.0f); v3 = fmaxf(v3, 0.0f);
            }
            if constexpr (MODE == 1) {
                // fp16 logits into L2-hot scratch
                size_t i0 = cOffZ + (size_t)mr * ldc + nc;
                size_t i1 = cOffZ + (size_t)(mr + 8) * ldc + nc;
                *reinterpret_cast<__half2*>(&Chi[i0]) =
                    __halves2half2(__float2half_rn(v0), __float2half_rn(v1));
                *reinterpret_cast<__half2*>(&Chi[i1]) =
                    __halves2half2(__float2half_rn(v2), __float2half_rn(v3));
            } else {
                if (Cf) {
                    *reinterpret_cast<float2*>(&Cf[cOffZ + (size_t)mr * ldc + nc]) =
                        make_float2(v0, v1);
                    *reinterpret_cast<float2*>(&Cf[cOffZ + (size_t)(mr + 8) * ldc + nc]) =
                        make_float2(v2, v3);
                }
                if (Chi) {
                    __half h0 = __float2half_rn(v0), h1 = __float2half_rn(v1);
                    __half h2 = __float2half_rn(v2), h3 = __float2half_rn(v3);
                    if (!transV) {
                        size_t i0 = cOffZ + (size_t)mr * ldc + nc;
                        size_t i1 = cOffZ + (size_t)(mr + 8) * ldc + nc;
                        *reinterpret_cast<__half2*>(&Chi[i0]) = __halves2half2(h0, h1);
                        *reinterpret_cast<__half2*>(&Chi[i1]) = __halves2half2(h2, h3);
                        if (Clo) {
                            __half l0 = __float2half_rn(v0 - __half2float(h0));
                            __half l1 = __float2half_rn(v1 - __half2float(h1));
                            __half l2 = __float2half_rn(v2 - __half2float(h2));
                            __half l3 = __float2half_rn(v3 - __half2float(h3));
                            *reinterpret_cast<__half2*>(&Clo[i0]) = __halves2half2(l0, l1);
                            *reinterpret_cast<__half2*>(&Clo[i1]) = __halves2half2(l2, l3);
                        }
                    } else {
#pragma unroll
                        for (int e = 0; e < 4; ++e) {
                            int rr = mr + (e >> 1) * 8;
                            int nn = nc + (e & 1);
                            size_t idx = ((size_t)(rr >> 11) * 16 + (size_t)(nn >> 6)) * 131072
                                       + (size_t)(nn & 63) * 2048 + (size_t)(rr & 2047);
                            __half hv = (e == 0) ? h0 : (e == 1) ? h1 : (e == 2) ? h2 : h3;
                            Chi[idx] = hv;
                        }
                    }
                }
            }
        }
    }
}

// ============================================================================
// Row softmax: fp16 logits scratch (L2-hot) -> fp32 attn output (streaming)
// ============================================================================
__global__ void __launch_bounds__(256) softmax_kernel(
    const __half* __restrict__ scratch, float* __restrict__ attn, int zbase)
{
    const int zloc = blockIdx.x >> 11;
    const int rr = blockIdx.x & 2047;
    const uint4* p = reinterpret_cast<const uint4*>(
        scratch + (size_t)zloc * 4194304 + (size_t)rr * 2048);
    float4* q = reinterpret_cast<float4*>(
        attn + (size_t)(zbase + zloc) * 4194304 + (size_t)rr * 2048);
    const int tid = threadIdx.x;

    uint4 raw = p[tid];                    // 8 halves
    __half2 h2v[4];
    h2v[0] = *reinterpret_cast<__half2*>(&raw.x);
    h2v[1] = *reinterpret_cast<__half2*>(&raw.y);
    h2v[2] = *reinterpret_cast<__half2*>(&raw.z);
    h2v[3] = *reinterpret_cast<__half2*>(&raw.w);
    float v[8];
#pragma unroll
    for (int j = 0; j < 4; ++j) {
        float2 f = __half22float2(h2v[j]);
        v[2 * j] = f.x; v[2 * j + 1] = f.y;
    }

    float mx = v[0];
#pragma unroll
    for (int j = 1; j < 8; ++j) mx = fmaxf(mx, v[j]);
#pragma unroll
    for (int o = 16; o; o >>= 1) mx = fmaxf(mx, __shfl_xor_sync(0xffffffffu, mx, o));

    __shared__ float smax[8], ssum[8];
    if ((tid & 31) == 0) smax[tid >> 5] = mx;
    __syncthreads();
    float m = smax[0];
#pragma unroll
    for (int i = 1; i < 8; i++) m = fmaxf(m, smax[i]);

    float s = 0.0f;
#pragma unroll
    for (int j = 0; j < 8; ++j) { v[j] = __expf(v[j] - m); s += v[j]; }
#pragma unroll
    for (int o = 16; o; o >>= 1) s += __shfl_xor_sync(0xffffffffu, s, o);
    if ((tid & 31) == 0) ssum[tid >> 5] = s;
    __syncthreads();
    float tot = 0.0f;
#pragma unroll
    for (int i = 0; i < 8; i++) tot += ssum[i];
    const float inv = 1.0f / tot;

    float4 o0 = make_float4(v[0] * inv, v[1] * inv, v[2] * inv, v[3] * inv);
    float4 o1 = make_float4(v[4] * inv, v[5] * inv, v[6] * inv, v[7] * inv);
    __stcs(q + 2 * tid, o0);
    __stcs(q + 2 * tid + 1, o1);
}

// ============================================================================
// Launch
// ============================================================================
extern "C" void kernel_launch(void* const* d_in, const int* in_sizes, int n_in,
                              void* d_out, int out_size)
{
    const float* x   = (const float*)d_in[0];
    const float* Wq  = (const float*)d_in[1];
    const float* bq  = (const float*)d_in[2];
    const float* Wk  = (const float*)d_in[3];
    const float* bk  = (const float*)d_in[4];
    const float* Wv  = (const float*)d_in[5];
    const float* bv  = (const float*)d_in[6];
    const float* Wo  = (const float*)d_in[7];
    const float* bo  = (const float*)d_in[8];
    const float* M1  = (const float*)d_in[9];
    const float* bm1 = (const float*)d_in[10];
    const float* M2  = (const float*)d_in[11];
    const float* bm2 = (const float*)d_in[12];

    float* out  = (float*)d_out;                      // (2,1024,1024)
    float* attn = out + (size_t)2 * 1024 * 1024;      // (2,16,2048,2048)

    __half *wH, *enhHi, *enhLo, *hHi, *hLo, *qH, *kH, *vtH, *cxHi, *cxLo, *sc;
    cudaGetSymbolAddress((void**)&wH,   g_w_h);
    cudaGetSymbolAddress((void**)&enhHi, g_enh_hi);
    cudaGetSymbolAddress((void**)&enhLo, g_enh_lo);
    cudaGetSymbolAddress((void**)&hHi,  g_h_hi);
    cudaGetSymbolAddress((void**)&hLo,  g_h_lo);
    cudaGetSymbolAddress((void**)&qH,   g_q_h);
    cudaGetSymbolAddress((void**)&kH,   g_k_h);
    cudaGetSymbolAddress((void**)&vtH,  g_vt_h);
    cudaGetSymbolAddress((void**)&cxHi, g_ctx_hi);
    cudaGetSymbolAddress((void**)&cxLo, g_ctx_lo);
    cudaGetSymbolAddress((void**)&sc,   g_sc);

    // one-time host resources (exist before graph capture; reused every call)
    static cudaStream_t s1 = nullptr;
    static cudaEvent_t evE, evV, evQK[8], evSm[8];
    if (!s1) {
        cudaStreamCreateWithFlags(&s1, cudaStreamNonBlocking);
        cudaEventCreateWithFlags(&evE, cudaEventDisableTiming);
        cudaEventCreateWithFlags(&evV, cudaEventDisableTiming);
        for (int g = 0; g < 8; ++g) {
            cudaEventCreateWithFlags(&evQK[g], cudaEventDisableTiming);
            cudaEventCreateWithFlags(&evSm[g], cudaEventDisableTiming);
        }
    }

    const size_t MW = 1048576;
    const int SMEM128_P2 = 2 * (2 * 10240 + 128 * 80);   // 61440
    const int SMEM128_P1 = 2 * (1 * 10240 + 128 * 80);   // 40960
    const int SMEM64_P1  = 2 * (1 * 10240 + 64 * 80);    // 30720
    cudaFuncSetAttribute(gemm2_mma<128, 0, 2>, cudaFuncAttributeMaxDynamicSharedMemorySize, SMEM128_P2);
    cudaFuncSetAttribute(gemm2_mma<128, 0, 1>, cudaFuncAttributeMaxDynamicSharedMemorySize, SMEM128_P1);
    cudaFuncSetAttribute(gemm2_mma<128, 1, 1>, cudaFuncAttributeMaxDynamicSharedMemorySize, SMEM128_P1);
    cudaFuncSetAttribute(gemm2_mma<64, 2, 1>,  cudaFuncAttributeMaxDynamicSharedMemorySize, SMEM64_P1);

    // 0) convert weights (single fp16) + x (hi/lo fp16)
    conv_w_kernel<<<dim3(1024, 6), 256>>>(M1, M2, Wq, Wk, Wv, Wo, wH);
    conv_kernel<<<2048, 256>>>(x, enhHi + 2097152, enhLo + 2097152, 524288);

    // 1) h = relu(x @ M1^T + bm1)   (2-pass)
    gemm2_mma<128, 0, 2><<<dim3(8, 16), 256, SMEM128_P2>>>(
        enhHi + 2097152, enhLo + 2097152, nullptr, wH + 0 * MW, bm1,
        nullptr, hHi, hLo, 1024, 1024, 1024, 1024, 1.0f, 1, 0, 0);
    // 2) enh[0:2048] = h @ M2^T + bm2   (2-pass)
    gemm2_mma<128, 0, 2><<<dim3(8, 16), 256, SMEM128_P2>>>(
        hHi, hLo, nullptr, wH + 1 * MW, bm2,
        nullptr, enhHi, enhLo, 1024, 1024, 1024, 1024, 1.0f, 0, 0, 0);

    // fork stream 1 after enh is ready
    cudaEventRecord(evE, 0);
    cudaStreamWaitEvent(s1, evE, 0);

    // 3) Q (1-pass), K (1-pass) on stream 0; V (1-pass, transposed) on stream 1
    gemm2_mma<128, 0, 1><<<dim3(8, 32), 256, SMEM128_P1>>>(
        enhHi, nullptr, nullptr, wH + 2 * MW, bq,
        nullptr, qH, nullptr, 1024, 1024, 1024, 1024, 1.0f, 0, 0, 0);
    gemm2_mma<128, 0, 1><<<dim3(8, 32), 256, SMEM128_P1>>>(
        enhHi, nullptr, nullptr, wH + 3 * MW, bk,
        nullptr, kH, nullptr, 1024, 1024, 1024, 1024, 1.0f, 0, 0, 0);
    gemm2_mma<128, 0, 1><<<dim3(8, 32), 256, SMEM128_P1, s1>>>(
        enhHi, nullptr, nullptr, wH + 4 * MW, bv,
        nullptr, vtH, nullptr, 1024, 1024, 1024, 1024, 1.0f, 0, 0, 1);
    cudaEventRecord(evV, s1);

    // 4+5) pipelined: QK_g (stream 0, fp16 logits -> buf g&1) ∥ softmax_{g-1} (stream 1)
    for (int g = 0; g < 8; ++g) {
        if (g >= 2) cudaStreamWaitEvent(0, evSm[g - 2], 0);   // buffer reuse
        gemm2_mma<128, 1, 1><<<dim3(16, 16, 4), 256, SMEM128_P1>>>(
            qH, nullptr, nullptr, kH, nullptr,
            nullptr, sc + (size_t)(g & 1) * 16777216, nullptr,
            64, 1024, 1024, 2048, 0.125f, 0, g * 4, 0);
        cudaEventRecord(evQK[g], 0);
        cudaStreamWaitEvent(s1, evQK[g], 0);
        softmax_kernel<<<8192, 256, 0, s1>>>(
            sc + (size_t)(g & 1) * 16777216, attn, g * 4);
        cudaEventRecord(evSm[g], s1);
    }
    cudaStreamWaitEvent(0, evSm[7], 0);   // s1 is serial: implies all softmax done
    cudaStreamWaitEvent(0, evV, 0);

    // 6) ctx = attn[., 1024:, :] @ V_bh  (1-pass, A = fp32 attn rounded in-kernel)
    gemm2_mma<64, 2, 1><<<dim3(1, 8, 32), 256, SMEM64_P1>>>(
        nullptr, nullptr, attn, vtH, nullptr,
        nullptr, cxHi, cxLo, 2048, 2048, 2048, 1024, 1.0f, 0, 0, 0);
    // 7) out = ctx @ Wo^T + bo  (2-pass, fp32 out)
    gemm2_mma<128, 0, 2><<<dim3(8, 16), 256, SMEM128_P2>>>(
        cxHi, cxLo, nullptr, wH + 5 * MW, bo,
        out, nullptr, nullptr, 1024, 1024, 1024, 1024, 1.0f, 0, 0, 0);
}